// round 1
// baseline (speedup 1.0000x reference)
#include <cuda_runtime.h>
#include <cstdint>
#include <cstddef>

// Problem constants
#define BATCH   16384
#define DIN     2048
#define DHALF   1024
#define H1DIM   512
#define H2DIM   128
#define NEXP    8
#define NCLS    10
#define NV      9        // 1 gate + 8 experts

// Scratch (allocation-free rule: __device__ globals)
__device__ float g_H1[(size_t)NV * BATCH * H1DIM];   // 9*16384*512 floats (~302MB)
__device__ float g_H2[(size_t)NV * BATCH * H2DIM];   // 9*16384*128 floats (~75MB)

// ---------------------------------------------------------------------------
// GEMM1: H1[v][m][h] = relu( sum_d X[m,d] * W1v[d,h] + b1v[h] )
// X = concat(fs, fp) read directly from the two halves.
// Tiles: BM=128, BN=128, BK=8, 256 threads, 8x8 per thread.
// Grid: x = 36 (9 v's * 4 n-tiles), y = 128 (m-tiles).
// ---------------------------------------------------------------------------
__global__ __launch_bounds__(256) void gemm1_kernel(
    const float* __restrict__ fs, const float* __restrict__ fp,
    const float* __restrict__ gW1, const float* __restrict__ gb1,
    const float* __restrict__ eW1, const float* __restrict__ eb1)
{
    __shared__ float As[8][128];
    __shared__ float Bs[8][128];

    const int bn = blockIdx.x;          // 0..35
    const int m0 = blockIdx.y * 128;
    const int v  = bn >> 2;             // 0..8
    const int n0 = (bn & 3) * 128;      // 0,128,256,384

    const float* W    = (v == 0) ? gW1 : (eW1 + (size_t)(v - 1) * DIN * H1DIM);
    const float* bias = (v == 0) ? gb1 : (eb1 + (size_t)(v - 1) * H1DIM);

    const int tid = threadIdx.x;
    const int tx  = tid & 15;           // 0..15 (n)
    const int ty  = tid >> 4;           // 0..15 (m)

    const int a_row = tid >> 1;         // 0..127
    const int a_col = (tid & 1) << 2;   // 0 or 4
    const int b_row = tid >> 5;         // 0..7
    const int b_col = (tid & 31) << 2;  // 0..124

    float acc[8][8];
    #pragma unroll
    for (int i = 0; i < 8; i++)
        #pragma unroll
        for (int j = 0; j < 8; j++)
            acc[i][j] = 0.0f;

    for (int kb = 0; kb < DIN; kb += 8) {
        // A tile load (split fs/fp; k-tiles of 8 never straddle the 1024 boundary)
        const float* arow;
        if (kb < DHALF)
            arow = fs + (size_t)(m0 + a_row) * DHALF + kb + a_col;
        else
            arow = fp + (size_t)(m0 + a_row) * DHALF + (kb - DHALF) + a_col;
        float4 av = *(const float4*)arow;
        As[a_col + 0][a_row] = av.x;
        As[a_col + 1][a_row] = av.y;
        As[a_col + 2][a_row] = av.z;
        As[a_col + 3][a_row] = av.w;

        // B tile load
        float4 bv4 = *(const float4*)(W + (size_t)(kb + b_row) * H1DIM + n0 + b_col);
        *(float4*)&Bs[b_row][b_col] = bv4;

        __syncthreads();

        #pragma unroll
        for (int k = 0; k < 8; k++) {
            float ar[8], br[8];
            *(float4*)&ar[0] = *(const float4*)&As[k][ty * 8];
            *(float4*)&ar[4] = *(const float4*)&As[k][ty * 8 + 4];
            *(float4*)&br[0] = *(const float4*)&Bs[k][tx * 8];
            *(float4*)&br[4] = *(const float4*)&Bs[k][tx * 8 + 4];
            #pragma unroll
            for (int i = 0; i < 8; i++)
                #pragma unroll
                for (int j = 0; j < 8; j++)
                    acc[i][j] += ar[i] * br[j];
        }
        __syncthreads();
    }

    // Epilogue: bias + relu, store to g_H1
    float bvals[8];
    #pragma unroll
    for (int j = 0; j < 8; j++) bvals[j] = bias[n0 + tx * 8 + j];

    #pragma unroll
    for (int i = 0; i < 8; i++) {
        int m = m0 + ty * 8 + i;
        float* o = g_H1 + ((size_t)v * BATCH + m) * H1DIM + n0 + tx * 8;
        float4 r0, r1;
        r0.x = fmaxf(acc[i][0] + bvals[0], 0.0f);
        r0.y = fmaxf(acc[i][1] + bvals[1], 0.0f);
        r0.z = fmaxf(acc[i][2] + bvals[2], 0.0f);
        r0.w = fmaxf(acc[i][3] + bvals[3], 0.0f);
        r1.x = fmaxf(acc[i][4] + bvals[4], 0.0f);
        r1.y = fmaxf(acc[i][5] + bvals[5], 0.0f);
        r1.z = fmaxf(acc[i][6] + bvals[6], 0.0f);
        r1.w = fmaxf(acc[i][7] + bvals[7], 0.0f);
        *(float4*)(o)     = r0;
        *(float4*)(o + 4) = r1;
    }
}

// ---------------------------------------------------------------------------
// GEMM2: H2[v][m][j] = relu( sum_h H1[v][m][h] * W2v[h,j] + b2v[j] )
// K=512, N=128 (single n-tile). Grid: x = 9 (v), y = 128 (m-tiles).
// ---------------------------------------------------------------------------
__global__ __launch_bounds__(256) void gemm2_kernel(
    const float* __restrict__ gW2, const float* __restrict__ gb2,
    const float* __restrict__ eW2, const float* __restrict__ eb2)
{
    __shared__ float As[8][128];
    __shared__ float Bs[8][128];

    const int v  = blockIdx.x;          // 0..8
    const int m0 = blockIdx.y * 128;

    const float* A    = g_H1 + (size_t)v * BATCH * H1DIM;
    const float* W    = (v == 0) ? gW2 : (eW2 + (size_t)(v - 1) * H1DIM * H2DIM);
    const float* bias = (v == 0) ? gb2 : (eb2 + (size_t)(v - 1) * H2DIM);

    const int tid = threadIdx.x;
    const int tx  = tid & 15;
    const int ty  = tid >> 4;

    const int a_row = tid >> 1;
    const int a_col = (tid & 1) << 2;
    const int b_row = tid >> 5;
    const int b_col = (tid & 31) << 2;

    float acc[8][8];
    #pragma unroll
    for (int i = 0; i < 8; i++)
        #pragma unroll
        for (int j = 0; j < 8; j++)
            acc[i][j] = 0.0f;

    for (int kb = 0; kb < H1DIM; kb += 8) {
        float4 av = *(const float4*)(A + (size_t)(m0 + a_row) * H1DIM + kb + a_col);
        As[a_col + 0][a_row] = av.x;
        As[a_col + 1][a_row] = av.y;
        As[a_col + 2][a_row] = av.z;
        As[a_col + 3][a_row] = av.w;

        float4 bv4 = *(const float4*)(W + (size_t)(kb + b_row) * H2DIM + b_col);
        *(float4*)&Bs[b_row][b_col] = bv4;

        __syncthreads();

        #pragma unroll
        for (int k = 0; k < 8; k++) {
            float ar[8], br[8];
            *(float4*)&ar[0] = *(const float4*)&As[k][ty * 8];
            *(float4*)&ar[4] = *(const float4*)&As[k][ty * 8 + 4];
            *(float4*)&br[0] = *(const float4*)&Bs[k][tx * 8];
            *(float4*)&br[4] = *(const float4*)&Bs[k][tx * 8 + 4];
            #pragma unroll
            for (int i = 0; i < 8; i++)
                #pragma unroll
                for (int j = 0; j < 8; j++)
                    acc[i][j] += ar[i] * br[j];
        }
        __syncthreads();
    }

    float bvals[8];
    #pragma unroll
    for (int j = 0; j < 8; j++) bvals[j] = bias[tx * 8 + j];

    #pragma unroll
    for (int i = 0; i < 8; i++) {
        int m = m0 + ty * 8 + i;
        float* o = g_H2 + ((size_t)v * BATCH + m) * H2DIM + tx * 8;
        float4 r0, r1;
        r0.x = fmaxf(acc[i][0] + bvals[0], 0.0f);
        r0.y = fmaxf(acc[i][1] + bvals[1], 0.0f);
        r0.z = fmaxf(acc[i][2] + bvals[2], 0.0f);
        r0.w = fmaxf(acc[i][3] + bvals[3], 0.0f);
        r1.x = fmaxf(acc[i][4] + bvals[4], 0.0f);
        r1.y = fmaxf(acc[i][5] + bvals[5], 0.0f);
        r1.z = fmaxf(acc[i][6] + bvals[6], 0.0f);
        r1.w = fmaxf(acc[i][7] + bvals[7], 0.0f);
        *(float4*)(o)     = r0;
        *(float4*)(o + 4) = r1;
    }
}

// ---------------------------------------------------------------------------
// Final: per token — gate logits->softmax, expert logits->log_softmax,
// gate-weighted sum. One warp per token, 4 warps per block.
// ---------------------------------------------------------------------------
__global__ __launch_bounds__(128) void final_kernel(
    const float* __restrict__ gW3, const float* __restrict__ gb3,
    const float* __restrict__ eW3, const float* __restrict__ eb3,
    float* __restrict__ out, int write_gate)
{
    const int warp = threadIdx.x >> 5;
    const int lane = threadIdx.x & 31;
    const int m = blockIdx.x * 4 + warp;
    if (m >= BATCH) return;

    // --- gate ---
    const float* hg = g_H2 + (size_t)m * H2DIM;   // v = 0
    float4 g4 = *(const float4*)(hg + lane * 4);
    const int h0 = lane * 4;

    float gl[NEXP];
    #pragma unroll
    for (int j = 0; j < NEXP; j++) {
        float p = g4.x * gW3[(h0 + 0) * NEXP + j]
                + g4.y * gW3[(h0 + 1) * NEXP + j]
                + g4.z * gW3[(h0 + 2) * NEXP + j]
                + g4.w * gW3[(h0 + 3) * NEXP + j];
        #pragma unroll
        for (int o = 16; o > 0; o >>= 1)
            p += __shfl_xor_sync(0xffffffffu, p, o);
        gl[j] = p + gb3[j];
    }
    float mx = gl[0];
    #pragma unroll
    for (int j = 1; j < NEXP; j++) mx = fmaxf(mx, gl[j]);
    float s = 0.0f;
    float gate[NEXP];
    #pragma unroll
    for (int j = 0; j < NEXP; j++) { gate[j] = expf(gl[j] - mx); s += gate[j]; }
    float inv = 1.0f / s;
    #pragma unroll
    for (int j = 0; j < NEXP; j++) gate[j] *= inv;

    // --- experts ---
    float outc[NCLS];
    #pragma unroll
    for (int c = 0; c < NCLS; c++) outc[c] = 0.0f;

    for (int e = 0; e < NEXP; e++) {
        const float* he = g_H2 + ((size_t)(1 + e) * BATCH + m) * H2DIM;
        float4 h4 = *(const float4*)(he + lane * 4);
        const float* W = eW3 + (size_t)e * H2DIM * NCLS;
        const float* bb = eb3 + e * NCLS;

        float le[NCLS];
        #pragma unroll
        for (int c = 0; c < NCLS; c++) {
            float p = h4.x * W[(h0 + 0) * NCLS + c]
                    + h4.y * W[(h0 + 1) * NCLS + c]
                    + h4.z * W[(h0 + 2) * NCLS + c]
                    + h4.w * W[(h0 + 3) * NCLS + c];
            #pragma unroll
            for (int o = 16; o > 0; o >>= 1)
                p += __shfl_xor_sync(0xffffffffu, p, o);
            le[c] = p + bb[c];
        }
        float mxe = le[0];
        #pragma unroll
        for (int c = 1; c < NCLS; c++) mxe = fmaxf(mxe, le[c]);
        float se = 0.0f;
        #pragma unroll
        for (int c = 0; c < NCLS; c++) se += expf(le[c] - mxe);
        float lse = mxe + logf(se);
        float ge = gate[e];
        #pragma unroll
        for (int c = 0; c < NCLS; c++) outc[c] += ge * (le[c] - lse);
    }

    // --- write outputs (all lanes hold identical values after reductions) ---
    if (lane < NCLS) out[(size_t)m * NCLS + lane] = outc[lane];
    if (write_gate && lane < NEXP) {
        float* gate_out = out + (size_t)BATCH * NCLS;
        gate_out[(size_t)m * NEXP + lane] = gate[lane];
    }
}

// ---------------------------------------------------------------------------
// Launch
// ---------------------------------------------------------------------------
extern "C" void kernel_launch(void* const* d_in, const int* in_sizes, int n_in,
                              void* d_out, int out_size)
{
    const float* fs  = (const float*)d_in[0];
    const float* fp  = (const float*)d_in[1];
    const float* gW1 = (const float*)d_in[2];
    const float* gb1 = (const float*)d_in[3];
    const float* gW2 = (const float*)d_in[4];
    const float* gb2 = (const float*)d_in[5];
    const float* gW3 = (const float*)d_in[6];
    const float* gb3 = (const float*)d_in[7];
    const float* eW1 = (const float*)d_in[8];
    const float* eb1 = (const float*)d_in[9];
    const float* eW2 = (const float*)d_in[10];
    const float* eb2 = (const float*)d_in[11];
    const float* eW3 = (const float*)d_in[12];
    const float* eb3 = (const float*)d_in[13];
    float* out = (float*)d_out;

    const int write_gate = (out_size >= BATCH * (NCLS + NEXP)) ? 1 : 0;

    // Layer 1: 9 stacked [2048->512] GEMMs with fused bias+relu
    {
        dim3 grid(NV * (H1DIM / 128), BATCH / 128);   // (36, 128)
        gemm1_kernel<<<grid, 256>>>(fs, fp, gW1, gb1, eW1, eb1);
    }
    // Layer 2: 9 stacked [512->128] GEMMs with fused bias+relu
    {
        dim3 grid(NV, BATCH / 128);                   // (9, 128)
        gemm2_kernel<<<grid, 256>>>(gW2, gb2, eW2, eb2);
    }
    // Layer 3 + softmax/log_softmax + gate-weighted sum
    {
        dim3 grid(BATCH / 4);                         // 4096 blocks, warp per token
        final_kernel<<<grid, 128>>>(gW3, gb3, eW3, eb3, out, write_gate);
    }
}

// round 3
// speedup vs baseline: 3.5447x; 3.5447x over previous
#include <cuda_runtime.h>
#include <cstdint>
#include <cstddef>

#define BATCH   16384
#define DIN     2048
#define DHALF   1024
#define H1DIM   512
#define H2DIM   128
#define NEXP    8
#define NCLS    10
#define NV      9

// ---------------------------------------------------------------------------
// Scratch (__device__ globals; allocation-free rule)
// g_At : A in mma A-fragment order  [mb128][kt256][mt8][lane32][4] (tf32-rounded)
// g_W1t: W1 in mma B-fragment order [v*4+nb][kt256][nt16][lane32][2]
// g_W2t: W2 in mma B-fragment order [v][kt64][nt16][lane32][2]
// g_H1t: H1 in mma A-fragment order [v][mb128][kt64][mt8][lane32][4] (tf32)
// g_H2 : plain row-major [v][m][128] fp32
// ---------------------------------------------------------------------------
__device__ float g_At [(size_t)BATCH * DIN];
__device__ float g_W1t[(size_t)NV * DIN * H1DIM];
__device__ float g_W2t[(size_t)NV * H1DIM * H2DIM];
__device__ float g_H1t[(size_t)NV * BATCH * H1DIM];
__device__ float g_H2 [(size_t)NV * BATCH * H2DIM];

// ---------------------------------------------------------------------------
// helpers
// ---------------------------------------------------------------------------
__device__ __forceinline__ float rna_tf32(float x) {
    uint32_t u;
    asm("cvt.rna.tf32.f32 %0, %1;" : "=r"(u) : "f"(x));
    return __uint_as_float(u);
}

__device__ __forceinline__ uint32_t smem_u32(const void* p) {
    uint32_t a;
    asm("{ .reg .u64 t; cvta.to.shared.u64 t, %1; cvt.u32.u64 %0, t; }" : "=r"(a) : "l"(p));
    return a;
}

#define CP16(ds, gs) \
    asm volatile("cp.async.cg.shared.global [%0], [%1], 16;" :: "r"(ds), "l"(gs))
#define CP_COMMIT()  asm volatile("cp.async.commit_group;" ::: "memory")
#define CP_WAIT1()   asm volatile("cp.async.wait_group 1;" ::: "memory")
#define CP_WAIT0()   asm volatile("cp.async.wait_group 0;" ::: "memory")

// m16n8k8 tf32 MMA, D += A*B  (row.col)
__device__ __forceinline__ void mma8(float* d, const uint32_t* a, const uint32_t* b) {
    asm volatile(
        "mma.sync.aligned.m16n8k8.row.col.f32.tf32.tf32.f32 "
        "{%0,%1,%2,%3}, {%4,%5,%6,%7}, {%8,%9}, {%0,%1,%2,%3};"
        : "+f"(d[0]), "+f"(d[1]), "+f"(d[2]), "+f"(d[3])
        : "r"(a[0]), "r"(a[1]), "r"(a[2]), "r"(a[3]), "r"(b[0]), "r"(b[1]));
}

// ---------------------------------------------------------------------------
// prep_A: concat(fs,fp) -> rna(tf32), A-fragment order
// grid (128 mb, 64 kq), 256 threads; warp w handles mtile w
// frag for lane l (r=l>>2, c=l&3): {A[r][c], A[r+8][c], A[r][c+4], A[r+8][c+4]}
// ---------------------------------------------------------------------------
__global__ __launch_bounds__(256) void prep_A(
    const float* __restrict__ fs, const float* __restrict__ fp)
{
    const int mb = blockIdx.x, kq = blockIdx.y;
    const int mt = threadIdx.x >> 5, l = threadIdx.x & 31;
    const int r = l >> 2, c = l & 3;
    const int m0 = mb * 128 + mt * 16;

    #pragma unroll
    for (int t = 0; t < 4; t++) {
        const int kt = kq * 4 + t;
        const int k0 = kt * 8;
        float4 v;
        {
            int k = k0 + c;
            const float* base = (k < DHALF) ? fs : fp;
            int kk = (k < DHALF) ? k : k - DHALF;
            v.x = rna_tf32(base[(size_t)(m0 + r)     * DHALF + kk]);
            v.y = rna_tf32(base[(size_t)(m0 + r + 8) * DHALF + kk]);
        }
        {
            int k = k0 + c + 4;
            const float* base = (k < DHALF) ? fs : fp;
            int kk = (k < DHALF) ? k : k - DHALF;
            v.z = rna_tf32(base[(size_t)(m0 + r)     * DHALF + kk]);
            v.w = rna_tf32(base[(size_t)(m0 + r + 8) * DHALF + kk]);
        }
        ((float4*)g_At)[(((size_t)mb * 256 + kt) * 8 + mt) * 32 + l] = v;
    }
}

// ---------------------------------------------------------------------------
// prep_W: W[k][n] -> rna(tf32), B-fragment order
// frag for lane l (c=l&3, g=l>>2): {W[k0+c][n], W[k0+c+4][n]}, n = n0+nt*8+g
// grid (K/32, N/128, NV), 256 threads; which: 1 -> g_W1t, 0 -> g_W2t
// ---------------------------------------------------------------------------
__global__ __launch_bounds__(256) void prep_W(
    const float* __restrict__ gw, const float* __restrict__ ew,
    int K, int N, int which)
{
    const int kq = blockIdx.x, nb = blockIdx.y, v = blockIdx.z;
    const float* W = (v == 0) ? gw : (ew + (size_t)(v - 1) * K * N);
    float* dst = which ? g_W1t : g_W2t;
    const int KT = K / 8, NB = N / 128;

    #pragma unroll
    for (int t = 0; t < 4; t++) {
        const int kt = kq * 4 + t, k0 = kt * 8;
        for (int idx = threadIdx.x; idx < 512; idx += 256) {
            const int nt = idx >> 5, l = idx & 31;
            const int c = l & 3, g = l >> 2;
            const int n = nb * 128 + nt * 8 + g;
            float2 v2;
            v2.x = rna_tf32(W[(size_t)(k0 + c)     * N + n]);
            v2.y = rna_tf32(W[(size_t)(k0 + c + 4) * N + n]);
            ((float2*)dst)[((((size_t)v * NB + nb) * KT + kt) * 16 + nt) * 32 + l] = v2;
        }
    }
}

// ---------------------------------------------------------------------------
// GEMM mainloop shared constants
// block tile 128(m) x 128(n) x 32(k) per stage; 8 warps (2m x 4n), warp 64x32
// smem per stage: A 16KB + B 16KB; 3 stages = 96KB
// ---------------------------------------------------------------------------
#define STAGES      3
#define STAGE_BYTES 32768
#define GEMM_SMEM   (STAGES * STAGE_BYTES)   // 98304; C-staging (67.6KB) fits

__device__ __forceinline__ void issue_stage(uint32_t sbase, int stage,
                                            const char* gA, const char* gB, int tid)
{
    uint32_t sA = sbase + stage * STAGE_BYTES;
    uint32_t sB = sA + 16384;
    #pragma unroll
    for (int j = 0; j < 4; j++)
        CP16(sA + (uint32_t)(tid + j * 256) * 16, gA + (size_t)(tid + j * 256) * 16);
    #pragma unroll
    for (int j = 0; j < 4; j++)
        CP16(sB + (uint32_t)(tid + j * 256) * 16, gB + (size_t)(tid + j * 256) * 16);
}

__device__ __forceinline__ void compute_stage(const char* smem, int stage,
                                              int wm, int wn, int l,
                                              float acc[4][4][4])
{
    const char* sA = smem + stage * STAGE_BYTES;
    const char* sB = sA + 16384;
    #pragma unroll
    for (int k8 = 0; k8 < 4; k8++) {
        uint32_t a[4][4], b[4][2];
        #pragma unroll
        for (int i = 0; i < 4; i++) {
            uint4 av = *(const uint4*)(sA + (((k8 * 8 + wm * 4 + i) * 32 + l) << 4));
            a[i][0] = av.x; a[i][1] = av.y; a[i][2] = av.z; a[i][3] = av.w;
        }
        #pragma unroll
        for (int j = 0; j < 4; j++) {
            uint2 bv = *(const uint2*)(sB + (((k8 * 16 + wn * 4 + j) * 32 + l) << 3));
            b[j][0] = bv.x; b[j][1] = bv.y;
        }
        #pragma unroll
        for (int i = 0; i < 4; i++)
            #pragma unroll
            for (int j = 0; j < 4; j++)
                mma8(acc[i][j], a[i], b[j]);
    }
}

// ---------------------------------------------------------------------------
// gemm1_tc: H1t[v] = fragA(rna(relu(A @ W1[v] + b1[v])))
// grid (36 = v*4+nb, 128 mb), 256 threads
// ---------------------------------------------------------------------------
__global__ __launch_bounds__(256, 1) void gemm1_tc(
    const float* __restrict__ gb1, const float* __restrict__ eb1)
{
    extern __shared__ __align__(16) char smem[];
    const uint32_t sbase = smem_u32(smem);
    const int tid = threadIdx.x;
    const int w = tid >> 5, l = tid & 31;
    const int wm = w >> 2, wn = w & 3;
    const int v = blockIdx.x >> 2, nb = blockIdx.x & 3;
    const int mb = blockIdx.y;

    const char* gA0 = (const char*)g_At + (size_t)mb * 256 * 4096;           // + kb*16384
    const char* gB0 = (const char*)g_W1t + (size_t)(v * 4 + nb) * 256 * 4096;

    float acc[4][4][4];
    #pragma unroll
    for (int i = 0; i < 4; i++)
        #pragma unroll
        for (int j = 0; j < 4; j++)
            #pragma unroll
            for (int q = 0; q < 4; q++) acc[i][j][q] = 0.0f;

    const int NKB = DIN / 32;   // 64
    issue_stage(sbase, 0, gA0, gB0, tid);                  CP_COMMIT();
    issue_stage(sbase, 1, gA0 + 16384, gB0 + 16384, tid);  CP_COMMIT();

    for (int kb = 0; kb < NKB; kb++) {
        CP_WAIT1();
        __syncthreads();
        if (kb + 2 < NKB)
            issue_stage(sbase, (kb + 2) % STAGES,
                        gA0 + (size_t)(kb + 2) * 16384,
                        gB0 + (size_t)(kb + 2) * 16384, tid);
        CP_COMMIT();
        compute_stage(smem, kb % STAGES, wm, wn, l, acc);
    }
    CP_WAIT0();
    __syncthreads();

    // ---- epilogue: bias+relu+rna via smem C (stride 132), then frag-A write ----
    float* C = (float*)smem;
    const float* bias = ((v == 0) ? gb1 : (eb1 + (size_t)(v - 1) * H1DIM)) + nb * 128;
    const int r = l >> 2, c2 = 2 * (l & 3);
    #pragma unroll
    for (int i = 0; i < 4; i++) {
        const int rr = wm * 64 + i * 16 + r;
        #pragma unroll
        for (int j = 0; j < 4; j++) {
            const int cc = wn * 32 + j * 8 + c2;
            const float b0 = __ldg(bias + cc), b1 = __ldg(bias + cc + 1);
            C[rr * 132 + cc]           = rna_tf32(fmaxf(acc[i][j][0] + b0, 0.0f));
            C[rr * 132 + cc + 1]       = rna_tf32(fmaxf(acc[i][j][1] + b1, 0.0f));
            C[(rr + 8) * 132 + cc]     = rna_tf32(fmaxf(acc[i][j][2] + b0, 0.0f));
            C[(rr + 8) * 132 + cc + 1] = rna_tf32(fmaxf(acc[i][j][3] + b1, 0.0f));
        }
    }
    __syncthreads();

    float4* dst = (float4*)g_H1t
                + ((((size_t)v * 128 + mb) * 64 + (size_t)nb * 16) * 8) * 32;
    #pragma unroll
    for (int t = 0; t < 16; t++) {
        const int idx = tid + t * 256;             // 0..4095
        const int kt = idx >> 8;
        const int rem = idx & 255;
        const int mt = rem >> 5, l2 = rem & 31;
        const int r2 = l2 >> 2, c3 = l2 & 3;
        float4 o;
        o.x = C[(mt * 16 + r2)     * 132 + kt * 8 + c3];
        o.y = C[(mt * 16 + r2 + 8) * 132 + kt * 8 + c3];
        o.z = C[(mt * 16 + r2)     * 132 + kt * 8 + c3 + 4];
        o.w = C[(mt * 16 + r2 + 8) * 132 + kt * 8 + c3 + 4];
        dst[(size_t)(kt * 8 + mt) * 32 + l2] = o;
    }
}

// ---------------------------------------------------------------------------
// gemm2_tc: H2[v] = relu(H1[v] @ W2[v] + b2[v]) -> plain fp32
// grid (9, 128 mb), 256 threads
// ---------------------------------------------------------------------------
__global__ __launch_bounds__(256, 1) void gemm2_tc(
    const float* __restrict__ gb2, const float* __restrict__ eb2)
{
    extern __shared__ __align__(16) char smem[];
    const uint32_t sbase = smem_u32(smem);
    const int tid = threadIdx.x;
    const int w = tid >> 5, l = tid & 31;
    const int wm = w >> 2, wn = w & 3;
    const int v = blockIdx.x;
    const int mb = blockIdx.y;

    const char* gA0 = (const char*)g_H1t + (size_t)(v * 128 + mb) * 64 * 4096;
    const char* gB0 = (const char*)g_W2t + (size_t)v * 64 * 4096;

    float acc[4][4][4];
    #pragma unroll
    for (int i = 0; i < 4; i++)
        #pragma unroll
        for (int j = 0; j < 4; j++)
            #pragma unroll
            for (int q = 0; q < 4; q++) acc[i][j][q] = 0.0f;

    const int NKB = H1DIM / 32;   // 16
    issue_stage(sbase, 0, gA0, gB0, tid);                  CP_COMMIT();
    issue_stage(sbase, 1, gA0 + 16384, gB0 + 16384, tid);  CP_COMMIT();

    for (int kb = 0; kb < NKB; kb++) {
        CP_WAIT1();
        __syncthreads();
        if (kb + 2 < NKB)
            issue_stage(sbase, (kb + 2) % STAGES,
                        gA0 + (size_t)(kb + 2) * 16384,
                        gB0 + (size_t)(kb + 2) * 16384, tid);
        CP_COMMIT();
        compute_stage(smem, kb % STAGES, wm, wn, l, acc);
    }
    CP_WAIT0();

    // ---- epilogue: bias + relu, direct plain store ----
    const float* bias = (v == 0) ? gb2 : (eb2 + (size_t)(v - 1) * H2DIM);
    const int r = l >> 2, c2 = 2 * (l & 3);
    #pragma unroll
    for (int i = 0; i < 4; i++) {
        const int m = mb * 128 + wm * 64 + i * 16 + r;
        float* o0 = g_H2 + ((size_t)v * BATCH + m) * H2DIM;
        float* o1 = g_H2 + ((size_t)v * BATCH + m + 8) * H2DIM;
        #pragma unroll
        for (int j = 0; j < 4; j++) {
            const int n = wn * 32 + j * 8 + c2;
            const float b0 = __ldg(bias + n), b1 = __ldg(bias + n + 1);
            float2 u, d;
            u.x = fmaxf(acc[i][j][0] + b0, 0.0f);
            u.y = fmaxf(acc[i][j][1] + b1, 0.0f);
            d.x = fmaxf(acc[i][j][2] + b0, 0.0f);
            d.y = fmaxf(acc[i][j][3] + b1, 0.0f);
            *(float2*)(o0 + n) = u;
            *(float2*)(o1 + n) = d;
        }
    }
}

// ---------------------------------------------------------------------------
// Final: gate softmax + expert log_softmax + gate-weighted sum
// ---------------------------------------------------------------------------
__global__ __launch_bounds__(128) void final_kernel(
    const float* __restrict__ gW3, const float* __restrict__ gb3,
    const float* __restrict__ eW3, const float* __restrict__ eb3,
    float* __restrict__ out, int write_gate)
{
    const int warp = threadIdx.x >> 5;
    const int lane = threadIdx.x & 31;
    const int m = blockIdx.x * 4 + warp;
    if (m >= BATCH) return;

    const float* hg = g_H2 + (size_t)m * H2DIM;
    float4 g4 = *(const float4*)(hg + lane * 4);
    const int h0 = lane * 4;

    float gl[NEXP];
    #pragma unroll
    for (int j = 0; j < NEXP; j++) {
        float p = g4.x * gW3[(h0 + 0) * NEXP + j]
                + g4.y * gW3[(h0 + 1) * NEXP + j]
                + g4.z * gW3[(h0 + 2) * NEXP + j]
                + g4.w * gW3[(h0 + 3) * NEXP + j];
        #pragma unroll
        for (int o = 16; o > 0; o >>= 1) p += __shfl_xor_sync(0xffffffffu, p, o);
        gl[j] = p + gb3[j];
    }
    float mx = gl[0];
    #pragma unroll
    for (int j = 1; j < NEXP; j++) mx = fmaxf(mx, gl[j]);
    float s = 0.0f, gate[NEXP];
    #pragma unroll
    for (int j = 0; j < NEXP; j++) { gate[j] = expf(gl[j] - mx); s += gate[j]; }
    float inv = 1.0f / s;
    #pragma unroll
    for (int j = 0; j < NEXP; j++) gate[j] *= inv;

    float outc[NCLS];
    #pragma unroll
    for (int c = 0; c < NCLS; c++) outc[c] = 0.0f;

    for (int e = 0; e < NEXP; e++) {
        const float* he = g_H2 + ((size_t)(1 + e) * BATCH + m) * H2DIM;
        float4 h4 = *(const float4*)(he + lane * 4);
        const float* W = eW3 + (size_t)e * H2DIM * NCLS;
        const float* bb = eb3 + e * NCLS;

        float le[NCLS];
        #pragma unroll
        for (int c = 0; c < NCLS; c++) {
            float p = h4.x * W[(h0 + 0) * NCLS + c]
                    + h4.y * W[(h0 + 1) * NCLS + c]
                    + h4.z * W[(h0 + 2) * NCLS + c]
                    + h4.w * W[(h0 + 3) * NCLS + c];
            #pragma unroll
            for (int o = 16; o > 0; o >>= 1) p += __shfl_xor_sync(0xffffffffu, p, o);
            le[c] = p + bb[c];
        }
        float mxe = le[0];
        #pragma unroll
        for (int c = 1; c < NCLS; c++) mxe = fmaxf(mxe, le[c]);
        float se = 0.0f;
        #pragma unroll
        for (int c = 0; c < NCLS; c++) se += expf(le[c] - mxe);
        float lse = mxe + logf(se);
        float ge = gate[e];
        #pragma unroll
        for (int c = 0; c < NCLS; c++) outc[c] += ge * (le[c] - lse);
    }

    if (lane < NCLS) out[(size_t)m * NCLS + lane] = outc[lane];
    if (write_gate && lane < NEXP) {
        float* gate_out = out + (size_t)BATCH * NCLS;
        gate_out[(size_t)m * NEXP + lane] = gate[lane];
    }
}

// ---------------------------------------------------------------------------
// Launch
// ---------------------------------------------------------------------------
extern "C" void kernel_launch(void* const* d_in, const int* in_sizes, int n_in,
                              void* d_out, int out_size)
{
    const float* fs  = (const float*)d_in[0];
    const float* fp  = (const float*)d_in[1];
    const float* gW1 = (const float*)d_in[2];
    const float* gb1 = (const float*)d_in[3];
    const float* gW2 = (const float*)d_in[4];
    const float* gb2 = (const float*)d_in[5];
    const float* gW3 = (const float*)d_in[6];
    const float* gb3 = (const float*)d_in[7];
    const float* eW1 = (const float*)d_in[8];
    const float* eb1 = (const float*)d_in[9];
    const float* eW2 = (const float*)d_in[10];
    const float* eb2 = (const float*)d_in[11];
    const float* eW3 = (const float*)d_in[12];
    const float* eb3 = (const float*)d_in[13];
    float* out = (float*)d_out;

    const int write_gate = (out_size >= BATCH * (NCLS + NEXP)) ? 1 : 0;

    static int attr_done = 0;
    if (!attr_done) {
        cudaFuncSetAttribute(gemm1_tc, cudaFuncAttributeMaxDynamicSharedMemorySize, GEMM_SMEM);
        cudaFuncSetAttribute(gemm2_tc, cudaFuncAttributeMaxDynamicSharedMemorySize, GEMM_SMEM);
        attr_done = 1;
    }

    // Prep: rna(tf32) + fragment-order retile
    prep_A<<<dim3(128, 64), 256>>>(fs, fp);
    prep_W<<<dim3(DIN / 32, H1DIM / 128, NV), 256>>>(gW1, eW1, DIN, H1DIM, 1);
    prep_W<<<dim3(H1DIM / 32, H2DIM / 128, NV), 256>>>(gW2, eW2, H1DIM, H2DIM, 0);

    // Layer 1 (tensor mma.sync tf32), writes H1 in gemm2 A-frag order
    gemm1_tc<<<dim3(NV * 4, BATCH / 128), 256, GEMM_SMEM>>>(gb1, eb1);
    // Layer 2
    gemm2_tc<<<dim3(NV, BATCH / 128), 256, GEMM_SMEM>>>(gb2, eb2);
    // Layer 3 + softmax/log_softmax + weighted sum
    final_kernel<<<BATCH / 4, 128>>>(gW3, gb3, eW3, eb3, out, write_gate);
}

// round 4
// speedup vs baseline: 6.9553x; 1.9621x over previous
#include <cuda_runtime.h>
#include <cuda_fp16.h>
#include <cstdint>
#include <cstddef>

#define BATCH   16384
#define DIN     2048
#define DHALF   1024
#define H1DIM   512
#define H2DIM   128
#define NEXP    8
#define NCLS    10
#define NV      9

// ---------------------------------------------------------------------------
// Scratch (__device__ globals)
// g_At : A fp16, A-frag order  [mb=128][kt=128][mt=8][lane=32] uint4   (67 MB)
// g_W1t: W1 fp16, B-frag order [v*4+nb=36][kt=128][nt=16][lane=32] uint2 (19 MB)
// g_W2t: W2 fp16, B-frag order [v=9][kt=32][nt=16][lane=32] uint2      (1.2 MB)
// g_H1t: H1 fp16, A-frag order [v=9][mb=128][kt=32][mt=8][lane=32] uint4 (151 MB)
// g_H2 : fp32 row-major [v][m][128]                                      (75 MB)
// ---------------------------------------------------------------------------
__device__ uint4 g_At [(size_t)128 * 128 * 8 * 32];
__device__ uint2 g_W1t[(size_t)36 * 128 * 16 * 32];
__device__ uint2 g_W2t[(size_t)9 * 32 * 16 * 32];
__device__ uint4 g_H1t[(size_t)9 * 128 * 32 * 8 * 32];
__device__ float g_H2 [(size_t)NV * BATCH * H2DIM];

// ---------------------------------------------------------------------------
// helpers
// ---------------------------------------------------------------------------
__device__ __forceinline__ uint32_t smem_u32(const void* p) {
    uint32_t a;
    asm("{ .reg .u64 t; cvta.to.shared.u64 t, %1; cvt.u32.u64 %0, t; }" : "=r"(a) : "l"(p));
    return a;
}

__device__ __forceinline__ uint32_t pack_h2(float x, float y) {
    __half2 h = __floats2half2_rn(x, y);
    return *(uint32_t*)&h;
}

#define CP16(ds, gs) \
    asm volatile("cp.async.cg.shared.global [%0], [%1], 16;" :: "r"(ds), "l"(gs))
#define CP_COMMIT()  asm volatile("cp.async.commit_group;" ::: "memory")
#define CP_WAIT1()   asm volatile("cp.async.wait_group 1;" ::: "memory")
#define CP_WAIT0()   asm volatile("cp.async.wait_group 0;" ::: "memory")

// m16n8k16 fp16 MMA, fp32 accum, D += A*B (row.col)
__device__ __forceinline__ void mma16(float* d, const uint32_t* a, const uint32_t* b) {
    asm volatile(
        "mma.sync.aligned.m16n8k16.row.col.f32.f16.f16.f32 "
        "{%0,%1,%2,%3}, {%4,%5,%6,%7}, {%8,%9}, {%0,%1,%2,%3};"
        : "+f"(d[0]), "+f"(d[1]), "+f"(d[2]), "+f"(d[3])
        : "r"(a[0]), "r"(a[1]), "r"(a[2]), "r"(a[3]), "r"(b[0]), "r"(b[1]));
}

// ---------------------------------------------------------------------------
// prep_A: concat(fs,fp) -> fp16 A-fragment order
// grid (128 mb, 32 kq), 256 threads (mt=tid>>5, lane=tid&31); 4 kt per block
// a0=(r,2c),(r,2c+1)  a1=(r+8,..)  a2=(r,2c+8),(r,2c+9)  a3=(r+8,..)
// ---------------------------------------------------------------------------
__global__ __launch_bounds__(256) void prep_A(
    const float* __restrict__ fs, const float* __restrict__ fp)
{
    const int mb = blockIdx.x, kq = blockIdx.y;
    const int mt = threadIdx.x >> 5, l = threadIdx.x & 31;
    const int r = l >> 2, c2 = 2 * (l & 3);
    const int m0 = mb * 128 + mt * 16;

    #pragma unroll
    for (int t = 0; t < 4; t++) {
        const int kt = kq * 4 + t;
        const int k0 = kt * 16;
        // k0 multiple of 16 -> [k0, k0+16) never straddles the 1024 boundary
        const float* base = (k0 < DHALF) ? fs : fp;
        const int kk = (k0 < DHALF) ? k0 : k0 - DHALF;

        float2 p0 = *(const float2*)(base + (size_t)(m0 + r)     * DHALF + kk + c2);
        float2 p1 = *(const float2*)(base + (size_t)(m0 + r + 8) * DHALF + kk + c2);
        float2 p2 = *(const float2*)(base + (size_t)(m0 + r)     * DHALF + kk + c2 + 8);
        float2 p3 = *(const float2*)(base + (size_t)(m0 + r + 8) * DHALF + kk + c2 + 8);

        uint4 o;
        o.x = pack_h2(p0.x, p0.y);
        o.y = pack_h2(p1.x, p1.y);
        o.z = pack_h2(p2.x, p2.y);
        o.w = pack_h2(p3.x, p3.y);
        g_At[(((size_t)mb * 128 + kt) * 8 + mt) * 32 + l] = o;
    }
}

// ---------------------------------------------------------------------------
// prep_W: W[k][n] -> fp16 B-fragment order
// b0=(k0+2c, n),(k0+2c+1, n)  b1=(k0+2c+8, n),(k0+2c+9, n);  n = nb*128+nt*8+g
// grid (K/16, N/128, NV), 256 threads; which: 1 -> g_W1t, 0 -> g_W2t
// ---------------------------------------------------------------------------
__global__ __launch_bounds__(256) void prep_W(
    const float* __restrict__ gw, const float* __restrict__ ew,
    int K, int N, int which)
{
    const int kt = blockIdx.x, nb = blockIdx.y, v = blockIdx.z;
    const float* W = (v == 0) ? gw : (ew + (size_t)(v - 1) * K * N);
    uint2* dst = which ? g_W1t : g_W2t;
    const int KT = K / 16, NB = N / 128;
    const int k0 = kt * 16;

    for (int idx = threadIdx.x; idx < 512; idx += 256) {
        const int nt = idx >> 5, l = idx & 31;
        const int c2 = 2 * (l & 3), g = l >> 2;
        const int n = nb * 128 + nt * 8 + g;
        uint2 o;
        o.x = pack_h2(W[(size_t)(k0 + c2)     * N + n], W[(size_t)(k0 + c2 + 1) * N + n]);
        o.y = pack_h2(W[(size_t)(k0 + c2 + 8) * N + n], W[(size_t)(k0 + c2 + 9) * N + n]);
        dst[((((size_t)v * NB + nb) * KT + kt) * 16 + nt) * 32 + l] = o;
    }
}

// ---------------------------------------------------------------------------
// GEMM mainloop: block 128m x 128n x 32k/stage; 8 warps (2m x 4n), warp 64x32
// stage = A 8KB + B 8KB = 16KB; 3 stages = 48KB -> 2 CTAs/SM
// ---------------------------------------------------------------------------
#define STAGES      3
#define STAGE_BYTES 16384
#define GEMM_SMEM   (STAGES * STAGE_BYTES)   // 49152

__device__ __forceinline__ void issue_stage(uint32_t sbase, int stage,
                                            const char* gA, const char* gB, int tid)
{
    uint32_t sA = sbase + stage * STAGE_BYTES;
    uint32_t sB = sA + 8192;
    #pragma unroll
    for (int j = 0; j < 2; j++)
        CP16(sA + (uint32_t)(tid + j * 256) * 16, gA + (size_t)(tid + j * 256) * 16);
    #pragma unroll
    for (int j = 0; j < 2; j++)
        CP16(sB + (uint32_t)(tid + j * 256) * 16, gB + (size_t)(tid + j * 256) * 16);
}

__device__ __forceinline__ void compute_stage(const char* smem, int stage,
                                              int wm, int wn, int l,
                                              float acc[4][4][4])
{
    const char* sA = smem + stage * STAGE_BYTES;
    const char* sB = sA + 8192;
    #pragma unroll
    for (int ks = 0; ks < 2; ks++) {   // two k16 tiles per stage
        uint32_t a[4][4], b[4][2];
        #pragma unroll
        for (int i = 0; i < 4; i++) {
            uint4 av = *(const uint4*)(sA + (((ks * 8 + wm * 4 + i) * 32 + l) << 4));
            a[i][0] = av.x; a[i][1] = av.y; a[i][2] = av.z; a[i][3] = av.w;
        }
        #pragma unroll
        for (int j = 0; j < 4; j++) {
            uint2 bv = *(const uint2*)(sB + (((ks * 16 + wn * 4 + j) * 32 + l) << 3));
            b[j][0] = bv.x; b[j][1] = bv.y;
        }
        #pragma unroll
        for (int i = 0; i < 4; i++)
            #pragma unroll
            for (int j = 0; j < 4; j++)
                mma16(acc[i][j], a[i], b[j]);
    }
}

// ---------------------------------------------------------------------------
// gemm1_tc: H1t[v] = fragA(fp16(relu(A @ W1[v] + b1[v])))
// grid (36 = v*4+nb, 128 mb), 256 threads
// epilogue: acc fragment == gemm2 A-fragment -> direct register pack + store
// ---------------------------------------------------------------------------
__global__ __launch_bounds__(256, 2) void gemm1_tc(
    const float* __restrict__ gb1, const float* __restrict__ eb1)
{
    extern __shared__ __align__(16) char smem[];
    const uint32_t sbase = smem_u32(smem);
    const int tid = threadIdx.x;
    const int w = tid >> 5, l = tid & 31;
    const int wm = w >> 2, wn = w & 3;
    const int v = blockIdx.x >> 2, nb = blockIdx.x & 3;
    const int mb = blockIdx.y;

    const char* gA0 = (const char*)g_At + (size_t)mb * 128 * 4096;           // + kb*8192
    const char* gB0 = (const char*)g_W1t + (size_t)(v * 4 + nb) * 128 * 4096;

    float acc[4][4][4];
    #pragma unroll
    for (int i = 0; i < 4; i++)
        #pragma unroll
        for (int j = 0; j < 4; j++)
            #pragma unroll
            for (int q = 0; q < 4; q++) acc[i][j][q] = 0.0f;

    const int NKB = DIN / 32;   // 64 stages
    issue_stage(sbase, 0, gA0, gB0, tid);                CP_COMMIT();
    issue_stage(sbase, 1, gA0 + 8192, gB0 + 8192, tid);  CP_COMMIT();

    for (int kb = 0; kb < NKB; kb++) {
        CP_WAIT1();
        __syncthreads();
        if (kb + 2 < NKB)
            issue_stage(sbase, (kb + 2) % STAGES,
                        gA0 + (size_t)(kb + 2) * 8192,
                        gB0 + (size_t)(kb + 2) * 8192, tid);
        CP_COMMIT();
        compute_stage(smem, kb % STAGES, wm, wn, l, acc);
    }
    CP_WAIT0();

    // ---- epilogue: bias+relu+fp16, direct A-fragment store for gemm2 ----
    const float* bias = ((v == 0) ? gb1 : (eb1 + (size_t)(v - 1) * H1DIM)) + nb * 128;
    const int c2 = 2 * (l & 3);
    #pragma unroll
    for (int i = 0; i < 4; i++) {
        const int mt = wm * 4 + i;
        #pragma unroll
        for (int jk = 0; jk < 2; jk++) {
            uint4 o;
            {
                const int j = 2 * jk;
                const int cc = wn * 32 + j * 8 + c2;
                const float b0 = __ldg(bias + cc), b1 = __ldg(bias + cc + 1);
                o.x = pack_h2(fmaxf(acc[i][j][0] + b0, 0.0f), fmaxf(acc[i][j][1] + b1, 0.0f));
                o.y = pack_h2(fmaxf(acc[i][j][2] + b0, 0.0f), fmaxf(acc[i][j][3] + b1, 0.0f));
            }
            {
                const int j = 2 * jk + 1;
                const int cc = wn * 32 + j * 8 + c2;
                const float b0 = __ldg(bias + cc), b1 = __ldg(bias + cc + 1);
                o.z = pack_h2(fmaxf(acc[i][j][0] + b0, 0.0f), fmaxf(acc[i][j][1] + b1, 0.0f));
                o.w = pack_h2(fmaxf(acc[i][j][2] + b0, 0.0f), fmaxf(acc[i][j][3] + b1, 0.0f));
            }
            const int kt = nb * 8 + wn * 2 + jk;
            g_H1t[((((size_t)v * 128 + mb) * 32 + kt) * 8 + mt) * 32 + l] = o;
        }
    }
}

// ---------------------------------------------------------------------------
// gemm2_tc: H2[v] = relu(H1[v] @ W2[v] + b2[v]) -> plain fp32
// grid (9, 128 mb), 256 threads
// ---------------------------------------------------------------------------
__global__ __launch_bounds__(256, 2) void gemm2_tc(
    const float* __restrict__ gb2, const float* __restrict__ eb2)
{
    extern __shared__ __align__(16) char smem[];
    const uint32_t sbase = smem_u32(smem);
    const int tid = threadIdx.x;
    const int w = tid >> 5, l = tid & 31;
    const int wm = w >> 2, wn = w & 3;
    const int v = blockIdx.x;
    const int mb = blockIdx.y;

    const char* gA0 = (const char*)g_H1t + (size_t)(v * 128 + mb) * 32 * 4096;
    const char* gB0 = (const char*)g_W2t + (size_t)v * 32 * 4096;

    float acc[4][4][4];
    #pragma unroll
    for (int i = 0; i < 4; i++)
        #pragma unroll
        for (int j = 0; j < 4; j++)
            #pragma unroll
            for (int q = 0; q < 4; q++) acc[i][j][q] = 0.0f;

    const int NKB = H1DIM / 32;   // 16 stages
    issue_stage(sbase, 0, gA0, gB0, tid);                CP_COMMIT();
    issue_stage(sbase, 1, gA0 + 8192, gB0 + 8192, tid);  CP_COMMIT();

    for (int kb = 0; kb < NKB; kb++) {
        CP_WAIT1();
        __syncthreads();
        if (kb + 2 < NKB)
            issue_stage(sbase, (kb + 2) % STAGES,
                        gA0 + (size_t)(kb + 2) * 8192,
                        gB0 + (size_t)(kb + 2) * 8192, tid);
        CP_COMMIT();
        compute_stage(smem, kb % STAGES, wm, wn, l, acc);
    }
    CP_WAIT0();

    // ---- epilogue: bias + relu, direct fp32 store ----
    const float* bias = (v == 0) ? gb2 : (eb2 + (size_t)(v - 1) * H2DIM);
    const int r = l >> 2, c2 = 2 * (l & 3);
    #pragma unroll
    for (int i = 0; i < 4; i++) {
        const int m = mb * 128 + wm * 64 + i * 16 + r;
        float* o0 = g_H2 + ((size_t)v * BATCH + m) * H2DIM;
        float* o1 = g_H2 + ((size_t)v * BATCH + m + 8) * H2DIM;
        #pragma unroll
        for (int j = 0; j < 4; j++) {
            const int n = wn * 32 + j * 8 + c2;
            const float b0 = __ldg(bias + n), b1 = __ldg(bias + n + 1);
            float2 u, d;
            u.x = fmaxf(acc[i][j][0] + b0, 0.0f);
            u.y = fmaxf(acc[i][j][1] + b1, 0.0f);
            d.x = fmaxf(acc[i][j][2] + b0, 0.0f);
            d.y = fmaxf(acc[i][j][3] + b1, 0.0f);
            *(float2*)(o0 + n) = u;
            *(float2*)(o1 + n) = d;
        }
    }
}

// ---------------------------------------------------------------------------
// Final: gate softmax + expert log_softmax + gate-weighted sum
// ---------------------------------------------------------------------------
__global__ __launch_bounds__(128) void final_kernel(
    const float* __restrict__ gW3, const float* __restrict__ gb3,
    const float* __restrict__ eW3, const float* __restrict__ eb3,
    float* __restrict__ out, int write_gate)
{
    const int warp = threadIdx.x >> 5;
    const int lane = threadIdx.x & 31;
    const int m = blockIdx.x * 4 + warp;
    if (m >= BATCH) return;

    const float* hg = g_H2 + (size_t)m * H2DIM;
    float4 g4 = *(const float4*)(hg + lane * 4);
    const int h0 = lane * 4;

    float gl[NEXP];
    #pragma unroll
    for (int j = 0; j < NEXP; j++) {
        float p = g4.x * gW3[(h0 + 0) * NEXP + j]
                + g4.y * gW3[(h0 + 1) * NEXP + j]
                + g4.z * gW3[(h0 + 2) * NEXP + j]
                + g4.w * gW3[(h0 + 3) * NEXP + j];
        #pragma unroll
        for (int o = 16; o > 0; o >>= 1) p += __shfl_xor_sync(0xffffffffu, p, o);
        gl[j] = p + gb3[j];
    }
    float mx = gl[0];
    #pragma unroll
    for (int j = 1; j < NEXP; j++) mx = fmaxf(mx, gl[j]);
    float s = 0.0f, gate[NEXP];
    #pragma unroll
    for (int j = 0; j < NEXP; j++) { gate[j] = expf(gl[j] - mx); s += gate[j]; }
    float inv = 1.0f / s;
    #pragma unroll
    for (int j = 0; j < NEXP; j++) gate[j] *= inv;

    float outc[NCLS];
    #pragma unroll
    for (int c = 0; c < NCLS; c++) outc[c] = 0.0f;

    for (int e = 0; e < NEXP; e++) {
        const float* he = g_H2 + ((size_t)(1 + e) * BATCH + m) * H2DIM;
        float4 h4 = *(const float4*)(he + lane * 4);
        const float* W = eW3 + (size_t)e * H2DIM * NCLS;
        const float* bb = eb3 + e * NCLS;

        float le[NCLS];
        #pragma unroll
        for (int c = 0; c < NCLS; c++) {
            float p = h4.x * W[(h0 + 0) * NCLS + c]
                    + h4.y * W[(h0 + 1) * NCLS + c]
                    + h4.z * W[(h0 + 2) * NCLS + c]
                    + h4.w * W[(h0 + 3) * NCLS + c];
            #pragma unroll
            for (int o = 16; o > 0; o >>= 1) p += __shfl_xor_sync(0xffffffffu, p, o);
            le[c] = p + bb[c];
        }
        float mxe = le[0];
        #pragma unroll
        for (int c = 1; c < NCLS; c++) mxe = fmaxf(mxe, le[c]);
        float se = 0.0f;
        #pragma unroll
        for (int c = 0; c < NCLS; c++) se += expf(le[c] - mxe);
        float lse = mxe + logf(se);
        float ge = gate[e];
        #pragma unroll
        for (int c = 0; c < NCLS; c++) outc[c] += ge * (le[c] - lse);
    }

    if (lane < NCLS) out[(size_t)m * NCLS + lane] = outc[lane];
    if (write_gate && lane < NEXP) {
        float* gate_out = out + (size_t)BATCH * NCLS;
        gate_out[(size_t)m * NEXP + lane] = gate[lane];
    }
}

// ---------------------------------------------------------------------------
// Launch
// ---------------------------------------------------------------------------
extern "C" void kernel_launch(void* const* d_in, const int* in_sizes, int n_in,
                              void* d_out, int out_size)
{
    const float* fs  = (const float*)d_in[0];
    const float* fp  = (const float*)d_in[1];
    const float* gW1 = (const float*)d_in[2];
    const float* gb1 = (const float*)d_in[3];
    const float* gW2 = (const float*)d_in[4];
    const float* gb2 = (const float*)d_in[5];
    const float* gW3 = (const float*)d_in[6];
    const float* gb3 = (const float*)d_in[7];
    const float* eW1 = (const float*)d_in[8];
    const float* eb1 = (const float*)d_in[9];
    const float* eW2 = (const float*)d_in[10];
    const float* eb2 = (const float*)d_in[11];
    const float* eW3 = (const float*)d_in[12];
    const float* eb3 = (const float*)d_in[13];
    float* out = (float*)d_out;

    const int write_gate = (out_size >= BATCH * (NCLS + NEXP)) ? 1 : 0;

    static int attr_done = 0;
    if (!attr_done) {
        cudaFuncSetAttribute(gemm1_tc, cudaFuncAttributeMaxDynamicSharedMemorySize, GEMM_SMEM);
        cudaFuncSetAttribute(gemm2_tc, cudaFuncAttributeMaxDynamicSharedMemorySize, GEMM_SMEM);
        attr_done = 1;
    }

    // Prep: fp16 + fragment-order retile
    prep_A<<<dim3(128, 32), 256>>>(fs, fp);
    prep_W<<<dim3(DIN / 16, H1DIM / 128, NV), 256>>>(gW1, eW1, DIN, H1DIM, 1);
    prep_W<<<dim3(H1DIM / 16, H2DIM / 128, NV), 256>>>(gW2, eW2, H1DIM, H2DIM, 0);

    // Layer 1 (fp16 tensor), writes H1 directly in gemm2 A-frag order
    gemm1_tc<<<dim3(NV * 4, BATCH / 128), 256, GEMM_SMEM>>>(gb1, eb1);
    // Layer 2
    gemm2_tc<<<dim3(NV, BATCH / 128), 256, GEMM_SMEM>>>(gb2, eb2);
    // Layer 3 + softmax/log_softmax + weighted sum
    final_kernel<<<BATCH / 4, 128>>>(gW3, gb3, eW3, eb3, out, write_gate);
}

// round 6
// speedup vs baseline: 7.8092x; 1.1228x over previous
#include <cuda_runtime.h>
#include <cuda_fp16.h>
#include <cstdint>
#include <cstddef>

#define BATCH   16384
#define DIN     2048
#define DHALF   1024
#define H1DIM   512
#define H2DIM   128
#define NEXP    8
#define NCLS    10
#define NV      9

// ---------------------------------------------------------------------------
// Scratch (__device__ globals)
// g_At : A fp16, A-frag order  [mb=128][kt=128][mt=8][lane=32] uint4   (67 MB)
// g_W1t: W1 fp16, B-frag order [v*4+nb=36][kt=128][nt=16][lane=32] uint2 (19 MB)
// g_W2t: W2 fp16, B-frag order [v=9][kt=32][nt=16][lane=32] uint2      (1.2 MB)
// g_H1t: H1 fp16, A-frag order [v=9][mb=128][kt=32][mt=8][lane=32] uint4 (151 MB)
// g_H2 : fp32 row-major [v][m][128]                                      (75 MB)
// ---------------------------------------------------------------------------
__device__ uint4 g_At [(size_t)128 * 128 * 8 * 32];
__device__ uint2 g_W1t[(size_t)36 * 128 * 16 * 32];
__device__ uint2 g_W2t[(size_t)9 * 32 * 16 * 32];
__device__ uint4 g_H1t[(size_t)9 * 128 * 32 * 8 * 32];
__device__ float g_H2 [(size_t)NV * BATCH * H2DIM];

// ---------------------------------------------------------------------------
// helpers
// ---------------------------------------------------------------------------
__device__ __forceinline__ uint32_t smem_u32(const void* p) {
    uint32_t a;
    asm("{ .reg .u64 t; cvta.to.shared.u64 t, %1; cvt.u32.u64 %0, t; }" : "=r"(a) : "l"(p));
    return a;
}

__device__ __forceinline__ uint32_t pack_h2(float x, float y) {
    __half2 h = __floats2half2_rn(x, y);
    return *(uint32_t*)&h;
}

#define CP16(ds, gs) \
    asm volatile("cp.async.cg.shared.global [%0], [%1], 16;" :: "r"(ds), "l"(gs))
#define CP_COMMIT()  asm volatile("cp.async.commit_group;" ::: "memory")
#define CP_WAIT2()   asm volatile("cp.async.wait_group 2;" ::: "memory")
#define CP_WAIT0()   asm volatile("cp.async.wait_group 0;" ::: "memory")

// m16n8k16 fp16 MMA, fp32 accum, D += A*B (row.col)
__device__ __forceinline__ void mma16(float* d, const uint32_t* a, const uint32_t* b) {
    asm volatile(
        "mma.sync.aligned.m16n8k16.row.col.f32.f16.f16.f32 "
        "{%0,%1,%2,%3}, {%4,%5,%6,%7}, {%8,%9}, {%0,%1,%2,%3};"
        : "+f"(d[0]), "+f"(d[1]), "+f"(d[2]), "+f"(d[3])
        : "r"(a[0]), "r"(a[1]), "r"(a[2]), "r"(a[3]), "r"(b[0]), "r"(b[1]));
}

// ---------------------------------------------------------------------------
// Merged prep: one grid covers prep_A (4096 blocks), prep_W1 (4608), prep_W2 (288)
// ---------------------------------------------------------------------------
#define PA_BLOCKS   4096     // 128 mb * 32 kq
#define PW1_BLOCKS  4608     // 128 kt * 4 nb * 9 v
#define PW2_BLOCKS  288      // 32 kt * 9 v
#define PREP_BLOCKS (PA_BLOCKS + PW1_BLOCKS + PW2_BLOCKS)

__device__ __forceinline__ void prep_W_body(
    const float* __restrict__ gw, const float* __restrict__ ew,
    uint2* dst, int K, int N, int kt, int nb, int v, int tid)
{
    const float* W = (v == 0) ? gw : (ew + (size_t)(v - 1) * K * N);
    const int KT = K / 16, NB = N / 128;
    const int k0 = kt * 16;

    for (int idx = tid; idx < 512; idx += 256) {
        const int nt = idx >> 5, l = idx & 31;
        const int c2 = 2 * (l & 3), g = l >> 2;
        const int n = nb * 128 + nt * 8 + g;
        uint2 o;
        o.x = pack_h2(W[(size_t)(k0 + c2)     * N + n], W[(size_t)(k0 + c2 + 1) * N + n]);
        o.y = pack_h2(W[(size_t)(k0 + c2 + 8) * N + n], W[(size_t)(k0 + c2 + 9) * N + n]);
        dst[((((size_t)v * NB + nb) * KT + kt) * 16 + nt) * 32 + l] = o;
    }
}

__global__ __launch_bounds__(256) void prep_all(
    const float* __restrict__ fs, const float* __restrict__ fp,
    const float* __restrict__ gW1, const float* __restrict__ eW1,
    const float* __restrict__ gW2, const float* __restrict__ eW2)
{
    const int bid = blockIdx.x;
    const int tid = threadIdx.x;

    if (bid < PA_BLOCKS) {
        // ---- prep_A: concat(fs,fp) -> fp16 A-fragment order ----
        const int mb = bid & 127, kq = bid >> 7;
        const int mt = tid >> 5, l = tid & 31;
        const int r = l >> 2, c2 = 2 * (l & 3);
        const int m0 = mb * 128 + mt * 16;

        #pragma unroll
        for (int t = 0; t < 4; t++) {
            const int kt = kq * 4 + t;
            const int k0 = kt * 16;
            const float* base = (k0 < DHALF) ? fs : fp;
            const int kk = (k0 < DHALF) ? k0 : k0 - DHALF;

            float2 p0 = *(const float2*)(base + (size_t)(m0 + r)     * DHALF + kk + c2);
            float2 p1 = *(const float2*)(base + (size_t)(m0 + r + 8) * DHALF + kk + c2);
            float2 p2 = *(const float2*)(base + (size_t)(m0 + r)     * DHALF + kk + c2 + 8);
            float2 p3 = *(const float2*)(base + (size_t)(m0 + r + 8) * DHALF + kk + c2 + 8);

            uint4 o;
            o.x = pack_h2(p0.x, p0.y);
            o.y = pack_h2(p1.x, p1.y);
            o.z = pack_h2(p2.x, p2.y);
            o.w = pack_h2(p3.x, p3.y);
            g_At[(((size_t)mb * 128 + kt) * 8 + mt) * 32 + l] = o;
        }
    } else if (bid < PA_BLOCKS + PW1_BLOCKS) {
        // ---- prep_W1 ----
        const int t = bid - PA_BLOCKS;
        const int kt = t & 127, nb = (t >> 7) & 3, v = t >> 9;
        prep_W_body(gW1, eW1, g_W1t, DIN, H1DIM, kt, nb, v, tid);
    } else {
        // ---- prep_W2 ----
        const int t = bid - (PA_BLOCKS + PW1_BLOCKS);
        const int kt = t & 31, v = t >> 5;
        prep_W_body(gW2, eW2, g_W2t, H1DIM, H2DIM, kt, 0, v, tid);
    }
}

// ---------------------------------------------------------------------------
// GEMM mainloop: block 128m x 128n x 32k/stage; 8 warps (2m x 4n), warp 64x32
// smem stage = A 8KB + B 8KB = 16KB; 4 stages = 64KB -> 2 CTAs/SM (128KB)
// GLOBAL stride per k-stage is 8KB in EACH of the A and B streams.
// prefetch distance 3, wait_group 2 -> 3 stages of memory slack
// ---------------------------------------------------------------------------
#define STAGES       4
#define STAGE_BYTES  16384   // smem footprint per stage (A+B)
#define GSTRIDE      8192    // global bytes per k-stage per stream
#define GEMM_SMEM    (STAGES * STAGE_BYTES)   // 65536

__device__ __forceinline__ void issue_stage(uint32_t sbase, int stage,
                                            const char* gA, const char* gB, int tid)
{
    uint32_t sA = sbase + stage * STAGE_BYTES;
    uint32_t sB = sA + 8192;
    #pragma unroll
    for (int j = 0; j < 2; j++)
        CP16(sA + (uint32_t)(tid + j * 256) * 16, gA + (size_t)(tid + j * 256) * 16);
    #pragma unroll
    for (int j = 0; j < 2; j++)
        CP16(sB + (uint32_t)(tid + j * 256) * 16, gB + (size_t)(tid + j * 256) * 16);
}

__device__ __forceinline__ void compute_stage(const char* smem, int stage,
                                              int wm, int wn, int l,
                                              float acc[4][4][4])
{
    const char* sA = smem + stage * STAGE_BYTES;
    const char* sB = sA + 8192;
    #pragma unroll
    for (int ks = 0; ks < 2; ks++) {   // two k16 tiles per stage
        uint32_t a[4][4], b[4][2];
        #pragma unroll
        for (int i = 0; i < 4; i++) {
            uint4 av = *(const uint4*)(sA + (((ks * 8 + wm * 4 + i) * 32 + l) << 4));
            a[i][0] = av.x; a[i][1] = av.y; a[i][2] = av.z; a[i][3] = av.w;
        }
        #pragma unroll
        for (int j = 0; j < 4; j++) {
            uint2 bv = *(const uint2*)(sB + (((ks * 16 + wn * 4 + j) * 32 + l) << 3));
            b[j][0] = bv.x; b[j][1] = bv.y;
        }
        #pragma unroll
        for (int i = 0; i < 4; i++)
            #pragma unroll
            for (int j = 0; j < 4; j++)
                mma16(acc[i][j], a[i], b[j]);
    }
}

// Shared mainloop: prologue issues stages 0..2, iter kb issues kb+3, waits <=2
template<int NKB>
__device__ __forceinline__ void gemm_mainloop(
    uint32_t sbase, const char* smem, const char* gA0, const char* gB0,
    int tid, int wm, int wn, int l, float acc[4][4][4])
{
    issue_stage(sbase, 0, gA0,               gB0,               tid); CP_COMMIT();
    issue_stage(sbase, 1, gA0 + 1 * GSTRIDE, gB0 + 1 * GSTRIDE, tid); CP_COMMIT();
    issue_stage(sbase, 2, gA0 + 2 * GSTRIDE, gB0 + 2 * GSTRIDE, tid); CP_COMMIT();

    #pragma unroll 4
    for (int kb = 0; kb < NKB; kb++) {
        CP_WAIT2();
        __syncthreads();
        if (kb + 3 < NKB)
            issue_stage(sbase, (kb + 3) & (STAGES - 1),
                        gA0 + (size_t)(kb + 3) * GSTRIDE,
                        gB0 + (size_t)(kb + 3) * GSTRIDE, tid);
        CP_COMMIT();
        compute_stage(smem, kb & (STAGES - 1), wm, wn, l, acc);
    }
    CP_WAIT0();
}

// ---------------------------------------------------------------------------
// gemm1_tc: H1t[v] = fragA(fp16(relu(A @ W1[v] + b1[v])))
// grid (36 = v*4+nb, 128 mb), 256 threads
// ---------------------------------------------------------------------------
__global__ __launch_bounds__(256, 2) void gemm1_tc(
    const float* __restrict__ gb1, const float* __restrict__ eb1)
{
    extern __shared__ __align__(16) char smem[];
    const uint32_t sbase = smem_u32(smem);
    const int tid = threadIdx.x;
    const int w = tid >> 5, l = tid & 31;
    const int wm = w >> 2, wn = w & 3;
    const int v = blockIdx.x >> 2, nb = blockIdx.x & 3;
    const int mb = blockIdx.y;

    const char* gA0 = (const char*)g_At + (size_t)mb * 128 * 4096;
    const char* gB0 = (const char*)g_W1t + (size_t)(v * 4 + nb) * 128 * 4096;

    float acc[4][4][4];
    #pragma unroll
    for (int i = 0; i < 4; i++)
        #pragma unroll
        for (int j = 0; j < 4; j++)
            #pragma unroll
            for (int q = 0; q < 4; q++) acc[i][j][q] = 0.0f;

    gemm_mainloop<DIN / 32>(sbase, smem, gA0, gB0, tid, wm, wn, l, acc);

    // ---- epilogue: bias+relu+fp16, direct A-fragment store for gemm2 ----
    const float* bias = ((v == 0) ? gb1 : (eb1 + (size_t)(v - 1) * H1DIM)) + nb * 128;
    const int c2 = 2 * (l & 3);
    #pragma unroll
    for (int i = 0; i < 4; i++) {
        const int mt = wm * 4 + i;
        #pragma unroll
        for (int jk = 0; jk < 2; jk++) {
            uint4 o;
            {
                const int j = 2 * jk;
                const int cc = wn * 32 + j * 8 + c2;
                const float b0 = __ldg(bias + cc), b1 = __ldg(bias + cc + 1);
                o.x = pack_h2(fmaxf(acc[i][j][0] + b0, 0.0f), fmaxf(acc[i][j][1] + b1, 0.0f));
                o.y = pack_h2(fmaxf(acc[i][j][2] + b0, 0.0f), fmaxf(acc[i][j][3] + b1, 0.0f));
            }
            {
                const int j = 2 * jk + 1;
                const int cc = wn * 32 + j * 8 + c2;
                const float b0 = __ldg(bias + cc), b1 = __ldg(bias + cc + 1);
                o.z = pack_h2(fmaxf(acc[i][j][0] + b0, 0.0f), fmaxf(acc[i][j][1] + b1, 0.0f));
                o.w = pack_h2(fmaxf(acc[i][j][2] + b0, 0.0f), fmaxf(acc[i][j][3] + b1, 0.0f));
            }
            const int kt = nb * 8 + wn * 2 + jk;
            g_H1t[((((size_t)v * 128 + mb) * 32 + kt) * 8 + mt) * 32 + l] = o;
        }
    }
}

// ---------------------------------------------------------------------------
// gemm2_tc: H2[v] = relu(H1[v] @ W2[v] + b2[v]) -> plain fp32
// grid (9, 128 mb), 256 threads
// ---------------------------------------------------------------------------
__global__ __launch_bounds__(256, 2) void gemm2_tc(
    const float* __restrict__ gb2, const float* __restrict__ eb2)
{
    extern __shared__ __align__(16) char smem[];
    const uint32_t sbase = smem_u32(smem);
    const int tid = threadIdx.x;
    const int w = tid >> 5, l = tid & 31;
    const int wm = w >> 2, wn = w & 3;
    const int v = blockIdx.x;
    const int mb = blockIdx.y;

    const char* gA0 = (const char*)g_H1t + (size_t)(v * 128 + mb) * 32 * 4096;
    const char* gB0 = (const char*)g_W2t + (size_t)v * 32 * 4096;

    float acc[4][4][4];
    #pragma unroll
    for (int i = 0; i < 4; i++)
        #pragma unroll
        for (int j = 0; j < 4; j++)
            #pragma unroll
            for (int q = 0; q < 4; q++) acc[i][j][q] = 0.0f;

    gemm_mainloop<H1DIM / 32>(sbase, smem, gA0, gB0, tid, wm, wn, l, acc);

    // ---- epilogue: bias + relu, direct fp32 store ----
    const float* bias = (v == 0) ? gb2 : (eb2 + (size_t)(v - 1) * H2DIM);
    const int r = l >> 2, c2 = 2 * (l & 3);
    #pragma unroll
    for (int i = 0; i < 4; i++) {
        const int m = mb * 128 + wm * 64 + i * 16 + r;
        float* o0 = g_H2 + ((size_t)v * BATCH + m) * H2DIM;
        float* o1 = g_H2 + ((size_t)v * BATCH + m + 8) * H2DIM;
        #pragma unroll
        for (int j = 0; j < 4; j++) {
            const int n = wn * 32 + j * 8 + c2;
            const float b0 = __ldg(bias + n), b1 = __ldg(bias + n + 1);
            float2 u, d;
            u.x = fmaxf(acc[i][j][0] + b0, 0.0f);
            u.y = fmaxf(acc[i][j][1] + b1, 0.0f);
            d.x = fmaxf(acc[i][j][2] + b0, 0.0f);
            d.y = fmaxf(acc[i][j][3] + b1, 0.0f);
            *(float2*)(o0 + n) = u;
            *(float2*)(o1 + n) = d;
        }
    }
}

// ---------------------------------------------------------------------------
// Final: gate softmax + expert log_softmax + gate-weighted sum
// ---------------------------------------------------------------------------
__global__ __launch_bounds__(128) void final_kernel(
    const float* __restrict__ gW3, const float* __restrict__ gb3,
    const float* __restrict__ eW3, const float* __restrict__ eb3,
    float* __restrict__ out, int write_gate)
{
    const int warp = threadIdx.x >> 5;
    const int lane = threadIdx.x & 31;
    const int m = blockIdx.x * 4 + warp;
    if (m >= BATCH) return;

    const float* hg = g_H2 + (size_t)m * H2DIM;
    float4 g4 = *(const float4*)(hg + lane * 4);
    const int h0 = lane * 4;

    float gl[NEXP];
    #pragma unroll
    for (int j = 0; j < NEXP; j++) {
        float p = g4.x * gW3[(h0 + 0) * NEXP + j]
                + g4.y * gW3[(h0 + 1) * NEXP + j]
                + g4.z * gW3[(h0 + 2) * NEXP + j]
                + g4.w * gW3[(h0 + 3) * NEXP + j];
        #pragma unroll
        for (int o = 16; o > 0; o >>= 1) p += __shfl_xor_sync(0xffffffffu, p, o);
        gl[j] = p + gb3[j];
    }
    float mx = gl[0];
    #pragma unroll
    for (int j = 1; j < NEXP; j++) mx = fmaxf(mx, gl[j]);
    float s = 0.0f, gate[NEXP];
    #pragma unroll
    for (int j = 0; j < NEXP; j++) { gate[j] = expf(gl[j] - mx); s += gate[j]; }
    float inv = 1.0f / s;
    #pragma unroll
    for (int j = 0; j < NEXP; j++) gate[j] *= inv;

    float outc[NCLS];
    #pragma unroll
    for (int c = 0; c < NCLS; c++) outc[c] = 0.0f;

    for (int e = 0; e < NEXP; e++) {
        const float* he = g_H2 + ((size_t)(1 + e) * BATCH + m) * H2DIM;
        float4 h4 = *(const float4*)(he + lane * 4);
        const float* W = eW3 + (size_t)e * H2DIM * NCLS;
        const float* bb = eb3 + e * NCLS;

        float le[NCLS];
        #pragma unroll
        for (int c = 0; c < NCLS; c++) {
            float p = h4.x * W[(h0 + 0) * NCLS + c]
                    + h4.y * W[(h0 + 1) * NCLS + c]
                    + h4.z * W[(h0 + 2) * NCLS + c]
                    + h4.w * W[(h0 + 3) * NCLS + c];
            #pragma unroll
            for (int o = 16; o > 0; o >>= 1) p += __shfl_xor_sync(0xffffffffu, p, o);
            le[c] = p + bb[c];
        }
        float mxe = le[0];
        #pragma unroll
        for (int c = 1; c < NCLS; c++) mxe = fmaxf(mxe, le[c]);
        float se = 0.0f;
        #pragma unroll
        for (int c = 0; c < NCLS; c++) se += expf(le[c] - mxe);
        float lse = mxe + logf(se);
        float ge = gate[e];
        #pragma unroll
        for (int c = 0; c < NCLS; c++) outc[c] += ge * (le[c] - lse);
    }

    if (lane < NCLS) out[(size_t)m * NCLS + lane] = outc[lane];
    if (write_gate && lane < NEXP) {
        float* gate_out = out + (size_t)BATCH * NCLS;
        gate_out[(size_t)m * NEXP + lane] = gate[lane];
    }
}

// ---------------------------------------------------------------------------
// Launch
// ---------------------------------------------------------------------------
extern "C" void kernel_launch(void* const* d_in, const int* in_sizes, int n_in,
                              void* d_out, int out_size)
{
    const float* fs  = (const float*)d_in[0];
    const float* fp  = (const float*)d_in[1];
    const float* gW1 = (const float*)d_in[2];
    const float* gb1 = (const float*)d_in[3];
    const float* gW2 = (const float*)d_in[4];
    const float* gb2 = (const float*)d_in[5];
    const float* gW3 = (const float*)d_in[6];
    const float* gb3 = (const float*)d_in[7];
    const float* eW1 = (const float*)d_in[8];
    const float* eb1 = (const float*)d_in[9];
    const float* eW2 = (const float*)d_in[10];
    const float* eb2 = (const float*)d_in[11];
    const float* eW3 = (const float*)d_in[12];
    const float* eb3 = (const float*)d_in[13];
    float* out = (float*)d_out;

    const int write_gate = (out_size >= BATCH * (NCLS + NEXP)) ? 1 : 0;

    static int attr_done = 0;
    if (!attr_done) {
        cudaFuncSetAttribute(gemm1_tc, cudaFuncAttributeMaxDynamicSharedMemorySize, GEMM_SMEM);
        cudaFuncSetAttribute(gemm2_tc, cudaFuncAttributeMaxDynamicSharedMemorySize, GEMM_SMEM);
        attr_done = 1;
    }

    // Prep (single merged launch): fp16 + fragment-order retile
    prep_all<<<PREP_BLOCKS, 256>>>(fs, fp, gW1, eW1, gW2, eW2);

    // Layer 1 (fp16 tensor), writes H1 directly in gemm2 A-frag order
    gemm1_tc<<<dim3(NV * 4, BATCH / 128), 256, GEMM_SMEM>>>(gb1, eb1);
    // Layer 2
    gemm2_tc<<<dim3(NV, BATCH / 128), 256, GEMM_SMEM>>>(gb2, eb2);
    // Layer 3 + softmax/log_softmax + weighted sum
    final_kernel<<<BATCH / 4, 128>>>(gW3, gb3, eW3, eb3, out, write_gate);
}

// round 7
// speedup vs baseline: 9.7274x; 1.2456x over previous
#include <cuda_runtime.h>
#include <cuda_fp16.h>
#include <cstdint>
#include <cstddef>

#define BATCH   16384
#define DIN     2048
#define DHALF   1024
#define H1DIM   512
#define H2DIM   128
#define NEXP    8
#define NCLS    10
#define NV      9

// ---------------------------------------------------------------------------
// Scratch (__device__ globals)
// ---------------------------------------------------------------------------
__device__ uint4 g_At [(size_t)128 * 128 * 8 * 32];
__device__ uint2 g_W1t[(size_t)36 * 128 * 16 * 32];
__device__ uint2 g_W2t[(size_t)9 * 32 * 16 * 32];
__device__ uint4 g_H1t[(size_t)9 * 128 * 32 * 8 * 32];
__device__ float g_H2 [(size_t)NV * BATCH * H2DIM];

// ---------------------------------------------------------------------------
// helpers
// ---------------------------------------------------------------------------
__device__ __forceinline__ uint32_t smem_u32(const void* p) {
    uint32_t a;
    asm("{ .reg .u64 t; cvta.to.shared.u64 t, %1; cvt.u32.u64 %0, t; }" : "=r"(a) : "l"(p));
    return a;
}

__device__ __forceinline__ uint32_t pack_h2(float x, float y) {
    __half2 h = __floats2half2_rn(x, y);
    return *(uint32_t*)&h;
}

#define CP16(ds, gs) \
    asm volatile("cp.async.cg.shared.global [%0], [%1], 16;" :: "r"(ds), "l"(gs))
#define CP_COMMIT()  asm volatile("cp.async.commit_group;" ::: "memory")
#define CP_WAIT2()   asm volatile("cp.async.wait_group 2;" ::: "memory")
#define CP_WAIT1()   asm volatile("cp.async.wait_group 1;" ::: "memory")
#define CP_WAIT0()   asm volatile("cp.async.wait_group 0;" ::: "memory")

// m16n8k16 fp16 MMA, fp32 accum, D += A*B (row.col)
__device__ __forceinline__ void mma16(float* d, const uint32_t* a, const uint32_t* b) {
    asm volatile(
        "mma.sync.aligned.m16n8k16.row.col.f32.f16.f16.f32 "
        "{%0,%1,%2,%3}, {%4,%5,%6,%7}, {%8,%9}, {%0,%1,%2,%3};"
        : "+f"(d[0]), "+f"(d[1]), "+f"(d[2]), "+f"(d[3])
        : "r"(a[0]), "r"(a[1]), "r"(a[2]), "r"(a[3]), "r"(b[0]), "r"(b[1]));
}

// ---------------------------------------------------------------------------
// Merged prep: one grid covers prep_A (4096 blocks), prep_W1 (4608), prep_W2 (288)
// ---------------------------------------------------------------------------
#define PA_BLOCKS   4096
#define PW1_BLOCKS  4608
#define PW2_BLOCKS  288
#define PREP_BLOCKS (PA_BLOCKS + PW1_BLOCKS + PW2_BLOCKS)

__device__ __forceinline__ void prep_W_body(
    const float* __restrict__ gw, const float* __restrict__ ew,
    uint2* dst, int K, int N, int kt, int nb, int v, int tid)
{
    const float* W = (v == 0) ? gw : (ew + (size_t)(v - 1) * K * N);
    const int KT = K / 16, NB = N / 128;
    const int k0 = kt * 16;

    for (int idx = tid; idx < 512; idx += 256) {
        const int nt = idx >> 5, l = idx & 31;
        const int c2 = 2 * (l & 3), g = l >> 2;
        const int n = nb * 128 + nt * 8 + g;
        uint2 o;
        o.x = pack_h2(W[(size_t)(k0 + c2)     * N + n], W[(size_t)(k0 + c2 + 1) * N + n]);
        o.y = pack_h2(W[(size_t)(k0 + c2 + 8) * N + n], W[(size_t)(k0 + c2 + 9) * N + n]);
        dst[((((size_t)v * NB + nb) * KT + kt) * 16 + nt) * 32 + l] = o;
    }
}

__global__ __launch_bounds__(256) void prep_all(
    const float* __restrict__ fs, const float* __restrict__ fp,
    const float* __restrict__ gW1, const float* __restrict__ eW1,
    const float* __restrict__ gW2, const float* __restrict__ eW2)
{
    const int bid = blockIdx.x;
    const int tid = threadIdx.x;

    if (bid < PA_BLOCKS) {
        const int mb = bid & 127, kq = bid >> 7;
        const int mt = tid >> 5, l = tid & 31;
        const int r = l >> 2, c2 = 2 * (l & 3);
        const int m0 = mb * 128 + mt * 16;

        #pragma unroll
        for (int t = 0; t < 4; t++) {
            const int kt = kq * 4 + t;
            const int k0 = kt * 16;
            const float* base = (k0 < DHALF) ? fs : fp;
            const int kk = (k0 < DHALF) ? k0 : k0 - DHALF;

            float2 p0 = *(const float2*)(base + (size_t)(m0 + r)     * DHALF + kk + c2);
            float2 p1 = *(const float2*)(base + (size_t)(m0 + r + 8) * DHALF + kk + c2);
            float2 p2 = *(const float2*)(base + (size_t)(m0 + r)     * DHALF + kk + c2 + 8);
            float2 p3 = *(const float2*)(base + (size_t)(m0 + r + 8) * DHALF + kk + c2 + 8);

            uint4 o;
            o.x = pack_h2(p0.x, p0.y);
            o.y = pack_h2(p1.x, p1.y);
            o.z = pack_h2(p2.x, p2.y);
            o.w = pack_h2(p3.x, p3.y);
            g_At[(((size_t)mb * 128 + kt) * 8 + mt) * 32 + l] = o;
        }
    } else if (bid < PA_BLOCKS + PW1_BLOCKS) {
        const int t = bid - PA_BLOCKS;
        const int kt = t & 127, nb = (t >> 7) & 3, v = t >> 9;
        prep_W_body(gW1, eW1, g_W1t, DIN, H1DIM, kt, nb, v, tid);
    } else {
        const int t = bid - (PA_BLOCKS + PW1_BLOCKS);
        const int kt = t & 31, v = t >> 5;
        prep_W_body(gW2, eW2, g_W2t, H1DIM, H2DIM, kt, 0, v, tid);
    }
}

// ---------------------------------------------------------------------------
// GEMM mainloop (unchanged from R6)
// ---------------------------------------------------------------------------
#define STAGES       4
#define STAGE_BYTES  16384
#define GSTRIDE      8192
#define GEMM_SMEM    (STAGES * STAGE_BYTES)

__device__ __forceinline__ void issue_stage(uint32_t sbase, int stage,
                                            const char* gA, const char* gB, int tid)
{
    uint32_t sA = sbase + stage * STAGE_BYTES;
    uint32_t sB = sA + 8192;
    #pragma unroll
    for (int j = 0; j < 2; j++)
        CP16(sA + (uint32_t)(tid + j * 256) * 16, gA + (size_t)(tid + j * 256) * 16);
    #pragma unroll
    for (int j = 0; j < 2; j++)
        CP16(sB + (uint32_t)(tid + j * 256) * 16, gB + (size_t)(tid + j * 256) * 16);
}

__device__ __forceinline__ void compute_stage(const char* smem, int stage,
                                              int wm, int wn, int l,
                                              float acc[4][4][4])
{
    const char* sA = smem + stage * STAGE_BYTES;
    const char* sB = sA + 8192;
    #pragma unroll
    for (int ks = 0; ks < 2; ks++) {
        uint32_t a[4][4], b[4][2];
        #pragma unroll
        for (int i = 0; i < 4; i++) {
            uint4 av = *(const uint4*)(sA + (((ks * 8 + wm * 4 + i) * 32 + l) << 4));
            a[i][0] = av.x; a[i][1] = av.y; a[i][2] = av.z; a[i][3] = av.w;
        }
        #pragma unroll
        for (int j = 0; j < 4; j++) {
            uint2 bv = *(const uint2*)(sB + (((ks * 16 + wn * 4 + j) * 32 + l) << 3));
            b[j][0] = bv.x; b[j][1] = bv.y;
        }
        #pragma unroll
        for (int i = 0; i < 4; i++)
            #pragma unroll
            for (int j = 0; j < 4; j++)
                mma16(acc[i][j], a[i], b[j]);
    }
}

template<int NKB>
__device__ __forceinline__ void gemm_mainloop(
    uint32_t sbase, const char* smem, const char* gA0, const char* gB0,
    int tid, int wm, int wn, int l, float acc[4][4][4])
{
    issue_stage(sbase, 0, gA0,               gB0,               tid); CP_COMMIT();
    issue_stage(sbase, 1, gA0 + 1 * GSTRIDE, gB0 + 1 * GSTRIDE, tid); CP_COMMIT();
    issue_stage(sbase, 2, gA0 + 2 * GSTRIDE, gB0 + 2 * GSTRIDE, tid); CP_COMMIT();

    #pragma unroll 4
    for (int kb = 0; kb < NKB; kb++) {
        CP_WAIT2();
        __syncthreads();
        if (kb + 3 < NKB)
            issue_stage(sbase, (kb + 3) & (STAGES - 1),
                        gA0 + (size_t)(kb + 3) * GSTRIDE,
                        gB0 + (size_t)(kb + 3) * GSTRIDE, tid);
        CP_COMMIT();
        compute_stage(smem, kb & (STAGES - 1), wm, wn, l, acc);
    }
    CP_WAIT0();
}

// ---------------------------------------------------------------------------
// gemm1_tc (unchanged from R6)
// ---------------------------------------------------------------------------
__global__ __launch_bounds__(256, 2) void gemm1_tc(
    const float* __restrict__ gb1, const float* __restrict__ eb1)
{
    extern __shared__ __align__(16) char smem[];
    const uint32_t sbase = smem_u32(smem);
    const int tid = threadIdx.x;
    const int w = tid >> 5, l = tid & 31;
    const int wm = w >> 2, wn = w & 3;
    const int v = blockIdx.x >> 2, nb = blockIdx.x & 3;
    const int mb = blockIdx.y;

    const char* gA0 = (const char*)g_At + (size_t)mb * 128 * 4096;
    const char* gB0 = (const char*)g_W1t + (size_t)(v * 4 + nb) * 128 * 4096;

    float acc[4][4][4];
    #pragma unroll
    for (int i = 0; i < 4; i++)
        #pragma unroll
        for (int j = 0; j < 4; j++)
            #pragma unroll
            for (int q = 0; q < 4; q++) acc[i][j][q] = 0.0f;

    gemm_mainloop<DIN / 32>(sbase, smem, gA0, gB0, tid, wm, wn, l, acc);

    const float* bias = ((v == 0) ? gb1 : (eb1 + (size_t)(v - 1) * H1DIM)) + nb * 128;
    const int c2 = 2 * (l & 3);
    #pragma unroll
    for (int i = 0; i < 4; i++) {
        const int mt = wm * 4 + i;
        #pragma unroll
        for (int jk = 0; jk < 2; jk++) {
            uint4 o;
            {
                const int j = 2 * jk;
                const int cc = wn * 32 + j * 8 + c2;
                const float b0 = __ldg(bias + cc), b1 = __ldg(bias + cc + 1);
                o.x = pack_h2(fmaxf(acc[i][j][0] + b0, 0.0f), fmaxf(acc[i][j][1] + b1, 0.0f));
                o.y = pack_h2(fmaxf(acc[i][j][2] + b0, 0.0f), fmaxf(acc[i][j][3] + b1, 0.0f));
            }
            {
                const int j = 2 * jk + 1;
                const int cc = wn * 32 + j * 8 + c2;
                const float b0 = __ldg(bias + cc), b1 = __ldg(bias + cc + 1);
                o.z = pack_h2(fmaxf(acc[i][j][0] + b0, 0.0f), fmaxf(acc[i][j][1] + b1, 0.0f));
                o.w = pack_h2(fmaxf(acc[i][j][2] + b0, 0.0f), fmaxf(acc[i][j][3] + b1, 0.0f));
            }
            const int kt = nb * 8 + wn * 2 + jk;
            g_H1t[((((size_t)v * 128 + mb) * 32 + kt) * 8 + mt) * 32 + l] = o;
        }
    }
}

// ---------------------------------------------------------------------------
// gemm2_tc (unchanged from R6)
// ---------------------------------------------------------------------------
__global__ __launch_bounds__(256, 2) void gemm2_tc(
    const float* __restrict__ gb2, const float* __restrict__ eb2)
{
    extern __shared__ __align__(16) char smem[];
    const uint32_t sbase = smem_u32(smem);
    const int tid = threadIdx.x;
    const int w = tid >> 5, l = tid & 31;
    const int wm = w >> 2, wn = w & 3;
    const int v = blockIdx.x;
    const int mb = blockIdx.y;

    const char* gA0 = (const char*)g_H1t + (size_t)(v * 128 + mb) * 32 * 4096;
    const char* gB0 = (const char*)g_W2t + (size_t)v * 32 * 4096;

    float acc[4][4][4];
    #pragma unroll
    for (int i = 0; i < 4; i++)
        #pragma unroll
        for (int j = 0; j < 4; j++)
            #pragma unroll
            for (int q = 0; q < 4; q++) acc[i][j][q] = 0.0f;

    gemm_mainloop<H1DIM / 32>(sbase, smem, gA0, gB0, tid, wm, wn, l, acc);

    const float* bias = (v == 0) ? gb2 : (eb2 + (size_t)(v - 1) * H2DIM);
    const int r = l >> 2, c2 = 2 * (l & 3);
    #pragma unroll
    for (int i = 0; i < 4; i++) {
        const int m = mb * 128 + wm * 64 + i * 16 + r;
        float* o0 = g_H2 + ((size_t)v * BATCH + m) * H2DIM;
        float* o1 = g_H2 + ((size_t)v * BATCH + m + 8) * H2DIM;
        #pragma unroll
        for (int j = 0; j < 4; j++) {
            const int n = wn * 32 + j * 8 + c2;
            const float b0 = __ldg(bias + n), b1 = __ldg(bias + n + 1);
            float2 u, d;
            u.x = fmaxf(acc[i][j][0] + b0, 0.0f);
            u.y = fmaxf(acc[i][j][1] + b1, 0.0f);
            d.x = fmaxf(acc[i][j][2] + b0, 0.0f);
            d.y = fmaxf(acc[i][j][3] + b1, 0.0f);
            *(float2*)(o0 + n) = u;
            *(float2*)(o1 + n) = d;
        }
    }
}

// ---------------------------------------------------------------------------
// final_kernel (REWRITTEN): thread-per-token, smem-staged H2 tiles (cp.async
// double buffer), all W3 tables in smem. Block = 128 threads = 128 tokens.
// smem: 2 tiles [128][132] f32 (135168B) + gate W [128][8] (4096B)
//       + expert W [8][128][12] (49152B) = 188416B
// ---------------------------------------------------------------------------
#define FIN_TILE_STRIDE 132
#define FIN_TILE_BYTES  (128 * FIN_TILE_STRIDE * 4)          // 67584
#define FIN_WG_OFF      (2 * FIN_TILE_BYTES)                  // 135168
#define FIN_WE_OFF      (FIN_WG_OFF + 128 * 8 * 4)            // 139264
#define FIN_SMEM        (FIN_WE_OFF + 8 * 128 * 12 * 4)       // 188416

__global__ __launch_bounds__(128) void final_kernel(
    const float* __restrict__ gW3, const float* __restrict__ gb3,
    const float* __restrict__ eW3, const float* __restrict__ eb3,
    float* __restrict__ out, int write_gate)
{
    extern __shared__ __align__(16) char smem[];
    const uint32_t sbase = smem_u32(smem);
    const int tid = threadIdx.x;
    const int m0 = blockIdx.x * 128;
    const int m = m0 + tid;

    float* tile0 = (float*)smem;
    float* tile1 = (float*)(smem + FIN_TILE_BYTES);
    float* wg = (float*)(smem + FIN_WG_OFF);     // [128][8]
    float* we = (float*)(smem + FIN_WE_OFF);     // [8][128][12]

    // ---- load W3 tables to smem (once) ----
    for (int i = tid; i < 128 * 8; i += 128) wg[i] = gW3[i];
    for (int i = tid; i < 8 * 128 * NCLS; i += 128) {
        const int e = i / (128 * NCLS);
        const int rem = i - e * 128 * NCLS;
        const int k = rem / NCLS, c = rem - k * NCLS;
        we[(e * 128 + k) * 12 + c] = eW3[i];
    }

    // ---- tile loader: 16B chunks; thread does 32 chunks ----
    auto issue_tile = [&](uint32_t sdst, int v) {
        const float* src = g_H2 + (size_t)v * BATCH * H2DIM + (size_t)m0 * H2DIM;
        #pragma unroll
        for (int it = 0; it < 32; it++) {
            const int idx = tid + it * 128;     // 0..4095
            const int row = idx >> 5, c4 = idx & 31;
            CP16(sdst + (uint32_t)(row * FIN_TILE_STRIDE + c4 * 4) * 4,
                 src + (size_t)row * H2DIM + c4 * 4);
        }
    };

    const uint32_t st0 = sbase;
    const uint32_t st1 = sbase + FIN_TILE_BYTES;

    issue_tile(st0, 0); CP_COMMIT();

    float gate[NEXP];
    float outc[NCLS];
    #pragma unroll
    for (int c = 0; c < NCLS; c++) outc[c] = 0.0f;

    for (int v = 0; v < NV; v++) {
        if (v + 1 < NV) { issue_tile((v & 1) ? st0 : st1, v + 1); CP_COMMIT(); }
        if (v + 1 < NV) { CP_WAIT1(); } else { CP_WAIT0(); }
        __syncthreads();   // tile v visible to all; also W3 tables on v==0

        const float* row = ((v & 1) ? tile1 : tile0) + (size_t)tid * FIN_TILE_STRIDE;

        if (v == 0) {
            // gate: 8 logits, softmax
            float gl[NEXP];
            #pragma unroll
            for (int j = 0; j < NEXP; j++) gl[j] = __ldg(gb3 + j);
            #pragma unroll 8
            for (int k = 0; k < 128; k++) {
                const float h = row[k];
                const float4 w0 = *(const float4*)(wg + k * 8);
                const float4 w1 = *(const float4*)(wg + k * 8 + 4);
                gl[0] += h * w0.x; gl[1] += h * w0.y; gl[2] += h * w0.z; gl[3] += h * w0.w;
                gl[4] += h * w1.x; gl[5] += h * w1.y; gl[6] += h * w1.z; gl[7] += h * w1.w;
            }
            float mx = gl[0];
            #pragma unroll
            for (int j = 1; j < NEXP; j++) mx = fmaxf(mx, gl[j]);
            float s = 0.0f;
            #pragma unroll
            for (int j = 0; j < NEXP; j++) { gate[j] = expf(gl[j] - mx); s += gate[j]; }
            const float inv = 1.0f / s;
            #pragma unroll
            for (int j = 0; j < NEXP; j++) gate[j] *= inv;
        } else {
            const int e = v - 1;
            const float* w = we + (size_t)e * 128 * 12;
            float le[NCLS];
            #pragma unroll
            for (int c = 0; c < NCLS; c++) le[c] = __ldg(eb3 + e * NCLS + c);
            #pragma unroll 4
            for (int k = 0; k < 128; k++) {
                const float h = row[k];
                const float4 w0 = *(const float4*)(w + k * 12);
                const float4 w1 = *(const float4*)(w + k * 12 + 4);
                const float2 w2 = *(const float2*)(w + k * 12 + 8);
                le[0] += h * w0.x; le[1] += h * w0.y; le[2] += h * w0.z; le[3] += h * w0.w;
                le[4] += h * w1.x; le[5] += h * w1.y; le[6] += h * w1.z; le[7] += h * w1.w;
                le[8] += h * w2.x; le[9] += h * w2.y;
            }
            float mxe = le[0];
            #pragma unroll
            for (int c = 1; c < NCLS; c++) mxe = fmaxf(mxe, le[c]);
            float se = 0.0f;
            #pragma unroll
            for (int c = 0; c < NCLS; c++) se += expf(le[c] - mxe);
            const float lse = mxe + logf(se);
            const float ge = gate[e];
            #pragma unroll
            for (int c = 0; c < NCLS; c++) outc[c] += ge * (le[c] - lse);
        }
        __syncthreads();   // everyone done with tile (v&1) before it's refilled
    }

    // ---- write outputs ----
    #pragma unroll
    for (int c = 0; c < NCLS; c++) out[(size_t)m * NCLS + c] = outc[c];
    if (write_gate) {
        float* gate_out = out + (size_t)BATCH * NCLS;
        #pragma unroll
        for (int j = 0; j < NEXP; j++) gate_out[(size_t)m * NEXP + j] = gate[j];
    }
}

// ---------------------------------------------------------------------------
// Launch
// ---------------------------------------------------------------------------
extern "C" void kernel_launch(void* const* d_in, const int* in_sizes, int n_in,
                              void* d_out, int out_size)
{
    const float* fs  = (const float*)d_in[0];
    const float* fp  = (const float*)d_in[1];
    const float* gW1 = (const float*)d_in[2];
    const float* gb1 = (const float*)d_in[3];
    const float* gW2 = (const float*)d_in[4];
    const float* gb2 = (const float*)d_in[5];
    const float* gW3 = (const float*)d_in[6];
    const float* gb3 = (const float*)d_in[7];
    const float* eW1 = (const float*)d_in[8];
    const float* eb1 = (const float*)d_in[9];
    const float* eW2 = (const float*)d_in[10];
    const float* eb2 = (const float*)d_in[11];
    const float* eW3 = (const float*)d_in[12];
    const float* eb3 = (const float*)d_in[13];
    float* out = (float*)d_out;

    const int write_gate = (out_size >= BATCH * (NCLS + NEXP)) ? 1 : 0;

    static int attr_done = 0;
    if (!attr_done) {
        cudaFuncSetAttribute(gemm1_tc, cudaFuncAttributeMaxDynamicSharedMemorySize, GEMM_SMEM);
        cudaFuncSetAttribute(gemm2_tc, cudaFuncAttributeMaxDynamicSharedMemorySize, GEMM_SMEM);
        cudaFuncSetAttribute(final_kernel, cudaFuncAttributeMaxDynamicSharedMemorySize, FIN_SMEM);
        attr_done = 1;
    }

    // Prep (single merged launch): fp16 + fragment-order retile
    prep_all<<<PREP_BLOCKS, 256>>>(fs, fp, gW1, eW1, gW2, eW2);

    // Layer 1 (fp16 tensor), writes H1 directly in gemm2 A-frag order
    gemm1_tc<<<dim3(NV * 4, BATCH / 128), 256, GEMM_SMEM>>>(gb1, eb1);
    // Layer 2
    gemm2_tc<<<dim3(NV, BATCH / 128), 256, GEMM_SMEM>>>(gb2, eb2);
    // Layer 3 + softmax/log_softmax + weighted sum (thread-per-token, smem staged)
    final_kernel<<<BATCH / 128, 128, FIN_SMEM>>>(gW3, gb3, eW3, eb3, out, write_gate);
}

// round 8
// speedup vs baseline: 9.9963x; 1.0276x over previous
#include <cuda_runtime.h>
#include <cuda_fp16.h>
#include <cstdint>
#include <cstddef>

#define BATCH   16384
#define DIN     2048
#define DHALF   1024
#define H1DIM   512
#define H2DIM   128
#define NEXP    8
#define NCLS    10
#define NV      9

// ---------------------------------------------------------------------------
// Scratch (__device__ globals)
// ---------------------------------------------------------------------------
__device__ uint4 g_At [(size_t)128 * 128 * 8 * 32];
__device__ uint2 g_W1t[(size_t)36 * 128 * 16 * 32];
__device__ uint2 g_W2t[(size_t)9 * 32 * 16 * 32];
__device__ uint4 g_H1t[(size_t)9 * 128 * 32 * 8 * 32];
__device__ float g_H2 [(size_t)NV * BATCH * H2DIM];

// ---------------------------------------------------------------------------
// helpers
// ---------------------------------------------------------------------------
__device__ __forceinline__ uint32_t smem_u32(const void* p) {
    uint32_t a;
    asm("{ .reg .u64 t; cvta.to.shared.u64 t, %1; cvt.u32.u64 %0, t; }" : "=r"(a) : "l"(p));
    return a;
}

__device__ __forceinline__ uint32_t pack_h2(float x, float y) {
    __half2 h = __floats2half2_rn(x, y);
    return *(uint32_t*)&h;
}

#define CP16(ds, gs) \
    asm volatile("cp.async.cg.shared.global [%0], [%1], 16;" :: "r"(ds), "l"(gs))
#define CP_COMMIT()  asm volatile("cp.async.commit_group;" ::: "memory")
#define CP_WAIT2()   asm volatile("cp.async.wait_group 2;" ::: "memory")
#define CP_WAIT1()   asm volatile("cp.async.wait_group 1;" ::: "memory")
#define CP_WAIT0()   asm volatile("cp.async.wait_group 0;" ::: "memory")

// m16n8k16 fp16 MMA, fp32 accum, D += A*B (row.col)
__device__ __forceinline__ void mma16(float* d, const uint32_t* a, const uint32_t* b) {
    asm volatile(
        "mma.sync.aligned.m16n8k16.row.col.f32.f16.f16.f32 "
        "{%0,%1,%2,%3}, {%4,%5,%6,%7}, {%8,%9}, {%0,%1,%2,%3};"
        : "+f"(d[0]), "+f"(d[1]), "+f"(d[2]), "+f"(d[3])
        : "r"(a[0]), "r"(a[1]), "r"(a[2]), "r"(a[3]), "r"(b[0]), "r"(b[1]));
}

// ---------------------------------------------------------------------------
// Merged prep (unchanged from R7)
// ---------------------------------------------------------------------------
#define PA_BLOCKS   4096
#define PW1_BLOCKS  4608
#define PW2_BLOCKS  288
#define PREP_BLOCKS (PA_BLOCKS + PW1_BLOCKS + PW2_BLOCKS)

__device__ __forceinline__ void prep_W_body(
    const float* __restrict__ gw, const float* __restrict__ ew,
    uint2* dst, int K, int N, int kt, int nb, int v, int tid)
{
    const float* W = (v == 0) ? gw : (ew + (size_t)(v - 1) * K * N);
    const int KT = K / 16, NB = N / 128;
    const int k0 = kt * 16;

    for (int idx = tid; idx < 512; idx += 256) {
        const int nt = idx >> 5, l = idx & 31;
        const int c2 = 2 * (l & 3), g = l >> 2;
        const int n = nb * 128 + nt * 8 + g;
        uint2 o;
        o.x = pack_h2(W[(size_t)(k0 + c2)     * N + n], W[(size_t)(k0 + c2 + 1) * N + n]);
        o.y = pack_h2(W[(size_t)(k0 + c2 + 8) * N + n], W[(size_t)(k0 + c2 + 9) * N + n]);
        dst[((((size_t)v * NB + nb) * KT + kt) * 16 + nt) * 32 + l] = o;
    }
}

__global__ __launch_bounds__(256) void prep_all(
    const float* __restrict__ fs, const float* __restrict__ fp,
    const float* __restrict__ gW1, const float* __restrict__ eW1,
    const float* __restrict__ gW2, const float* __restrict__ eW2)
{
    const int bid = blockIdx.x;
    const int tid = threadIdx.x;

    if (bid < PA_BLOCKS) {
        const int mb = bid & 127, kq = bid >> 7;
        const int mt = tid >> 5, l = tid & 31;
        const int r = l >> 2, c2 = 2 * (l & 3);
        const int m0 = mb * 128 + mt * 16;

        #pragma unroll
        for (int t = 0; t < 4; t++) {
            const int kt = kq * 4 + t;
            const int k0 = kt * 16;
            const float* base = (k0 < DHALF) ? fs : fp;
            const int kk = (k0 < DHALF) ? k0 : k0 - DHALF;

            float2 p0 = *(const float2*)(base + (size_t)(m0 + r)     * DHALF + kk + c2);
            float2 p1 = *(const float2*)(base + (size_t)(m0 + r + 8) * DHALF + kk + c2);
            float2 p2 = *(const float2*)(base + (size_t)(m0 + r)     * DHALF + kk + c2 + 8);
            float2 p3 = *(const float2*)(base + (size_t)(m0 + r + 8) * DHALF + kk + c2 + 8);

            uint4 o;
            o.x = pack_h2(p0.x, p0.y);
            o.y = pack_h2(p1.x, p1.y);
            o.z = pack_h2(p2.x, p2.y);
            o.w = pack_h2(p3.x, p3.y);
            g_At[(((size_t)mb * 128 + kt) * 8 + mt) * 32 + l] = o;
        }
    } else if (bid < PA_BLOCKS + PW1_BLOCKS) {
        const int t = bid - PA_BLOCKS;
        const int kt = t & 127, nb = (t >> 7) & 3, v = t >> 9;
        prep_W_body(gW1, eW1, g_W1t, DIN, H1DIM, kt, nb, v, tid);
    } else {
        const int t = bid - (PA_BLOCKS + PW1_BLOCKS);
        const int kt = t & 31, v = t >> 5;
        prep_W_body(gW2, eW2, g_W2t, H1DIM, H2DIM, kt, 0, v, tid);
    }
}

// ---------------------------------------------------------------------------
// GEMM mainloop (unchanged from R7)
// ---------------------------------------------------------------------------
#define STAGES       4
#define STAGE_BYTES  16384
#define GSTRIDE      8192
#define GEMM_SMEM    (STAGES * STAGE_BYTES)

__device__ __forceinline__ void issue_stage(uint32_t sbase, int stage,
                                            const char* gA, const char* gB, int tid)
{
    uint32_t sA = sbase + stage * STAGE_BYTES;
    uint32_t sB = sA + 8192;
    #pragma unroll
    for (int j = 0; j < 2; j++)
        CP16(sA + (uint32_t)(tid + j * 256) * 16, gA + (size_t)(tid + j * 256) * 16);
    #pragma unroll
    for (int j = 0; j < 2; j++)
        CP16(sB + (uint32_t)(tid + j * 256) * 16, gB + (size_t)(tid + j * 256) * 16);
}

__device__ __forceinline__ void compute_stage(const char* smem, int stage,
                                              int wm, int wn, int l,
                                              float acc[4][4][4])
{
    const char* sA = smem + stage * STAGE_BYTES;
    const char* sB = sA + 8192;
    #pragma unroll
    for (int ks = 0; ks < 2; ks++) {
        uint32_t a[4][4], b[4][2];
        #pragma unroll
        for (int i = 0; i < 4; i++) {
            uint4 av = *(const uint4*)(sA + (((ks * 8 + wm * 4 + i) * 32 + l) << 4));
            a[i][0] = av.x; a[i][1] = av.y; a[i][2] = av.z; a[i][3] = av.w;
        }
        #pragma unroll
        for (int j = 0; j < 4; j++) {
            uint2 bv = *(const uint2*)(sB + (((ks * 16 + wn * 4 + j) * 32 + l) << 3));
            b[j][0] = bv.x; b[j][1] = bv.y;
        }
        #pragma unroll
        for (int i = 0; i < 4; i++)
            #pragma unroll
            for (int j = 0; j < 4; j++)
                mma16(acc[i][j], a[i], b[j]);
    }
}

template<int NKB>
__device__ __forceinline__ void gemm_mainloop(
    uint32_t sbase, const char* smem, const char* gA0, const char* gB0,
    int tid, int wm, int wn, int l, float acc[4][4][4])
{
    issue_stage(sbase, 0, gA0,               gB0,               tid); CP_COMMIT();
    issue_stage(sbase, 1, gA0 + 1 * GSTRIDE, gB0 + 1 * GSTRIDE, tid); CP_COMMIT();
    issue_stage(sbase, 2, gA0 + 2 * GSTRIDE, gB0 + 2 * GSTRIDE, tid); CP_COMMIT();

    #pragma unroll 4
    for (int kb = 0; kb < NKB; kb++) {
        CP_WAIT2();
        __syncthreads();
        if (kb + 3 < NKB)
            issue_stage(sbase, (kb + 3) & (STAGES - 1),
                        gA0 + (size_t)(kb + 3) * GSTRIDE,
                        gB0 + (size_t)(kb + 3) * GSTRIDE, tid);
        CP_COMMIT();
        compute_stage(smem, kb & (STAGES - 1), wm, wn, l, acc);
    }
    CP_WAIT0();
}

// ---------------------------------------------------------------------------
// gemm1_tc (unchanged from R7)
// ---------------------------------------------------------------------------
__global__ __launch_bounds__(256, 2) void gemm1_tc(
    const float* __restrict__ gb1, const float* __restrict__ eb1)
{
    extern __shared__ __align__(16) char smem[];
    const uint32_t sbase = smem_u32(smem);
    const int tid = threadIdx.x;
    const int w = tid >> 5, l = tid & 31;
    const int wm = w >> 2, wn = w & 3;
    const int v = blockIdx.x >> 2, nb = blockIdx.x & 3;
    const int mb = blockIdx.y;

    const char* gA0 = (const char*)g_At + (size_t)mb * 128 * 4096;
    const char* gB0 = (const char*)g_W1t + (size_t)(v * 4 + nb) * 128 * 4096;

    float acc[4][4][4];
    #pragma unroll
    for (int i = 0; i < 4; i++)
        #pragma unroll
        for (int j = 0; j < 4; j++)
            #pragma unroll
            for (int q = 0; q < 4; q++) acc[i][j][q] = 0.0f;

    gemm_mainloop<DIN / 32>(sbase, smem, gA0, gB0, tid, wm, wn, l, acc);

    const float* bias = ((v == 0) ? gb1 : (eb1 + (size_t)(v - 1) * H1DIM)) + nb * 128;
    const int c2 = 2 * (l & 3);
    #pragma unroll
    for (int i = 0; i < 4; i++) {
        const int mt = wm * 4 + i;
        #pragma unroll
        for (int jk = 0; jk < 2; jk++) {
            uint4 o;
            {
                const int j = 2 * jk;
                const int cc = wn * 32 + j * 8 + c2;
                const float b0 = __ldg(bias + cc), b1 = __ldg(bias + cc + 1);
                o.x = pack_h2(fmaxf(acc[i][j][0] + b0, 0.0f), fmaxf(acc[i][j][1] + b1, 0.0f));
                o.y = pack_h2(fmaxf(acc[i][j][2] + b0, 0.0f), fmaxf(acc[i][j][3] + b1, 0.0f));
            }
            {
                const int j = 2 * jk + 1;
                const int cc = wn * 32 + j * 8 + c2;
                const float b0 = __ldg(bias + cc), b1 = __ldg(bias + cc + 1);
                o.z = pack_h2(fmaxf(acc[i][j][0] + b0, 0.0f), fmaxf(acc[i][j][1] + b1, 0.0f));
                o.w = pack_h2(fmaxf(acc[i][j][2] + b0, 0.0f), fmaxf(acc[i][j][3] + b1, 0.0f));
            }
            const int kt = nb * 8 + wn * 2 + jk;
            g_H1t[((((size_t)v * 128 + mb) * 32 + kt) * 8 + mt) * 32 + l] = o;
        }
    }
}

// ---------------------------------------------------------------------------
// gemm2_tc (unchanged from R7)
// ---------------------------------------------------------------------------
__global__ __launch_bounds__(256, 2) void gemm2_tc(
    const float* __restrict__ gb2, const float* __restrict__ eb2)
{
    extern __shared__ __align__(16) char smem[];
    const uint32_t sbase = smem_u32(smem);
    const int tid = threadIdx.x;
    const int w = tid >> 5, l = tid & 31;
    const int wm = w >> 2, wn = w & 3;
    const int v = blockIdx.x;
    const int mb = blockIdx.y;

    const char* gA0 = (const char*)g_H1t + (size_t)(v * 128 + mb) * 32 * 4096;
    const char* gB0 = (const char*)g_W2t + (size_t)v * 32 * 4096;

    float acc[4][4][4];
    #pragma unroll
    for (int i = 0; i < 4; i++)
        #pragma unroll
        for (int j = 0; j < 4; j++)
            #pragma unroll
            for (int q = 0; q < 4; q++) acc[i][j][q] = 0.0f;

    gemm_mainloop<H1DIM / 32>(sbase, smem, gA0, gB0, tid, wm, wn, l, acc);

    const float* bias = (v == 0) ? gb2 : (eb2 + (size_t)(v - 1) * H2DIM);
    const int r = l >> 2, c2 = 2 * (l & 3);
    #pragma unroll
    for (int i = 0; i < 4; i++) {
        const int m = mb * 128 + wm * 64 + i * 16 + r;
        float* o0 = g_H2 + ((size_t)v * BATCH + m) * H2DIM;
        float* o1 = g_H2 + ((size_t)v * BATCH + m + 8) * H2DIM;
        #pragma unroll
        for (int j = 0; j < 4; j++) {
            const int n = wn * 32 + j * 8 + c2;
            const float b0 = __ldg(bias + n), b1 = __ldg(bias + n + 1);
            float2 u, d;
            u.x = fmaxf(acc[i][j][0] + b0, 0.0f);
            u.y = fmaxf(acc[i][j][1] + b1, 0.0f);
            d.x = fmaxf(acc[i][j][2] + b0, 0.0f);
            d.y = fmaxf(acc[i][j][3] + b1, 0.0f);
            *(float2*)(o0 + n) = u;
            *(float2*)(o1 + n) = d;
        }
    }
}

// ---------------------------------------------------------------------------
// final_kernel v3: 256 threads = 128 tokens x 2 k-halves.
// half 0: k in [0,64), combines partials, softmax/log-softmax, writes out.
// half 1: k in [64,128), writes partial sums to smem.
// Tiles staged via cp.async double buffer; h read as float4 (conflict-free).
// smem: 2 tiles [128][132] f32 + wg [128][8] + we [8][128][12] + sp [128][12]
// ---------------------------------------------------------------------------
#define FIN_TILE_STRIDE 132
#define FIN_TILE_BYTES  (128 * FIN_TILE_STRIDE * 4)          // 67584
#define FIN_WG_OFF      (2 * FIN_TILE_BYTES)                  // 135168
#define FIN_WE_OFF      (FIN_WG_OFF + 128 * 8 * 4)            // 139264
#define FIN_SP_OFF      (FIN_WE_OFF + 8 * 128 * 12 * 4)       // 188416
#define FIN_SMEM        (FIN_SP_OFF + 128 * 12 * 4)           // 194560

__global__ __launch_bounds__(256) void final_kernel(
    const float* __restrict__ gW3, const float* __restrict__ gb3,
    const float* __restrict__ eW3, const float* __restrict__ eb3,
    float* __restrict__ out, int write_gate)
{
    extern __shared__ __align__(16) char smem[];
    const uint32_t sbase = smem_u32(smem);
    const int tid = threadIdx.x;
    const int half = tid >> 7;          // 0 or 1
    const int tt = tid & 127;           // token within block
    const int m0 = blockIdx.x * 128;

    float* tile0 = (float*)smem;
    float* tile1 = (float*)(smem + FIN_TILE_BYTES);
    float* wg = (float*)(smem + FIN_WG_OFF);     // [128][8]
    float* we = (float*)(smem + FIN_WE_OFF);     // [8][128][12]
    float* sp = (float*)(smem + FIN_SP_OFF);     // [128][12] partials

    // ---- load W3 tables to smem (once, all 256 threads) ----
    for (int i = tid; i < 128 * 8; i += 256) wg[i] = gW3[i];
    for (int i = tid; i < 8 * 128 * NCLS; i += 256) {
        const int e = i / (128 * NCLS);
        const int rem = i - e * 128 * NCLS;
        const int k = rem / NCLS, c = rem - k * NCLS;
        we[(e * 128 + k) * 12 + c] = eW3[i];
    }

    // ---- tile loader: 4096 16B chunks; 16 per thread ----
    auto issue_tile = [&](uint32_t sdst, int v) {
        const float* src = g_H2 + (size_t)v * BATCH * H2DIM + (size_t)m0 * H2DIM;
        #pragma unroll
        for (int it = 0; it < 16; it++) {
            const int idx = tid + it * 256;     // 0..4095
            const int row = idx >> 5, c4 = idx & 31;
            CP16(sdst + (uint32_t)(row * FIN_TILE_STRIDE + c4 * 4) * 4,
                 src + (size_t)row * H2DIM + c4 * 4);
        }
    };

    const uint32_t st0 = sbase;
    const uint32_t st1 = sbase + FIN_TILE_BYTES;

    issue_tile(st0, 0); CP_COMMIT();

    float gate[NEXP];
    float outc[NCLS];
    #pragma unroll
    for (int c = 0; c < NCLS; c++) outc[c] = 0.0f;

    for (int v = 0; v < NV; v++) {
        if (v + 1 < NV) { issue_tile((v & 1) ? st0 : st1, v + 1); CP_COMMIT(); }
        if (v + 1 < NV) { CP_WAIT1(); } else { CP_WAIT0(); }
        __syncthreads();   // tile v visible; W3 tables ready on v==0

        // this thread's k-half of its token's row
        const float* row = ((v & 1) ? tile1 : tile0)
                         + (size_t)tt * FIN_TILE_STRIDE + half * 64;

        if (v == 0) {
            // ---- gate partial: 8 logits over 64 k ----
            float gl[NEXP];
            #pragma unroll
            for (int j = 0; j < NEXP; j++) gl[j] = 0.0f;
            const float* wgh = wg + half * 64 * 8;
            #pragma unroll 4
            for (int k4 = 0; k4 < 16; k4++) {
                const float4 h4 = *(const float4*)(row + k4 * 4);
                const float hv[4] = { h4.x, h4.y, h4.z, h4.w };
                #pragma unroll
                for (int q = 0; q < 4; q++) {
                    const float h = hv[q];
                    const float4 w0 = *(const float4*)(wgh + (k4 * 4 + q) * 8);
                    const float4 w1 = *(const float4*)(wgh + (k4 * 4 + q) * 8 + 4);
                    gl[0] += h * w0.x; gl[1] += h * w0.y; gl[2] += h * w0.z; gl[3] += h * w0.w;
                    gl[4] += h * w1.x; gl[5] += h * w1.y; gl[6] += h * w1.z; gl[7] += h * w1.w;
                }
            }
            if (half == 1) {
                #pragma unroll
                for (int j = 0; j < NEXP; j++) sp[tt * 12 + j] = gl[j];
            }
            __syncthreads();
            if (half == 0) {
                #pragma unroll
                for (int j = 0; j < NEXP; j++)
                    gl[j] += sp[tt * 12 + j] + __ldg(gb3 + j);
                float mx = gl[0];
                #pragma unroll
                for (int j = 1; j < NEXP; j++) mx = fmaxf(mx, gl[j]);
                float s = 0.0f;
                #pragma unroll
                for (int j = 0; j < NEXP; j++) { gate[j] = expf(gl[j] - mx); s += gate[j]; }
                const float inv = 1.0f / s;
                #pragma unroll
                for (int j = 0; j < NEXP; j++) gate[j] *= inv;
            }
        } else {
            // ---- expert partial: 10 logits over 64 k ----
            const int e = v - 1;
            const float* w = we + ((size_t)e * 128 + half * 64) * 12;
            float le[NCLS];
            #pragma unroll
            for (int c = 0; c < NCLS; c++) le[c] = 0.0f;
            #pragma unroll 4
            for (int k4 = 0; k4 < 16; k4++) {
                const float4 h4 = *(const float4*)(row + k4 * 4);
                const float hv[4] = { h4.x, h4.y, h4.z, h4.w };
                #pragma unroll
                for (int q = 0; q < 4; q++) {
                    const float h = hv[q];
                    const float* wk = w + (k4 * 4 + q) * 12;
                    const float4 w0 = *(const float4*)(wk);
                    const float4 w1 = *(const float4*)(wk + 4);
                    const float2 w2 = *(const float2*)(wk + 8);
                    le[0] += h * w0.x; le[1] += h * w0.y; le[2] += h * w0.z; le[3] += h * w0.w;
                    le[4] += h * w1.x; le[5] += h * w1.y; le[6] += h * w1.z; le[7] += h * w1.w;
                    le[8] += h * w2.x; le[9] += h * w2.y;
                }
            }
            if (half == 1) {
                #pragma unroll
                for (int c = 0; c < NCLS; c++) sp[tt * 12 + c] = le[c];
            }
            __syncthreads();
            if (half == 0) {
                #pragma unroll
                for (int c = 0; c < NCLS; c++)
                    le[c] += sp[tt * 12 + c] + __ldg(eb3 + e * NCLS + c);
                float mxe = le[0];
                #pragma unroll
                for (int c = 1; c < NCLS; c++) mxe = fmaxf(mxe, le[c]);
                float se = 0.0f;
                #pragma unroll
                for (int c = 0; c < NCLS; c++) se += expf(le[c] - mxe);
                const float lse = mxe + logf(se);
                const float ge = gate[e];
                #pragma unroll
                for (int c = 0; c < NCLS; c++) outc[c] += ge * (le[c] - lse);
            }
        }
        __syncthreads();   // sp and tile (v&1) reusable
    }

    // ---- write outputs (half 0 owns the combined results) ----
    if (half == 0) {
        const int m = m0 + tt;
        #pragma unroll
        for (int c = 0; c < NCLS; c++) out[(size_t)m * NCLS + c] = outc[c];
        if (write_gate) {
            float* gate_out = out + (size_t)BATCH * NCLS;
            #pragma unroll
            for (int j = 0; j < NEXP; j++) gate_out[(size_t)m * NEXP + j] = gate[j];
        }
    }
}

// ---------------------------------------------------------------------------
// Launch
// ---------------------------------------------------------------------------
extern "C" void kernel_launch(void* const* d_in, const int* in_sizes, int n_in,
                              void* d_out, int out_size)
{
    const float* fs  = (const float*)d_in[0];
    const float* fp  = (const float*)d_in[1];
    const float* gW1 = (const float*)d_in[2];
    const float* gb1 = (const float*)d_in[3];
    const float* gW2 = (const float*)d_in[4];
    const float* gb2 = (const float*)d_in[5];
    const float* gW3 = (const float*)d_in[6];
    const float* gb3 = (const float*)d_in[7];
    const float* eW1 = (const float*)d_in[8];
    const float* eb1 = (const float*)d_in[9];
    const float* eW2 = (const float*)d_in[10];
    const float* eb2 = (const float*)d_in[11];
    const float* eW3 = (const float*)d_in[12];
    const float* eb3 = (const float*)d_in[13];
    float* out = (float*)d_out;

    const int write_gate = (out_size >= BATCH * (NCLS + NEXP)) ? 1 : 0;

    static int attr_done = 0;
    if (!attr_done) {
        cudaFuncSetAttribute(gemm1_tc, cudaFuncAttributeMaxDynamicSharedMemorySize, GEMM_SMEM);
        cudaFuncSetAttribute(gemm2_tc, cudaFuncAttributeMaxDynamicSharedMemorySize, GEMM_SMEM);
        cudaFuncSetAttribute(final_kernel, cudaFuncAttributeMaxDynamicSharedMemorySize, FIN_SMEM);
        attr_done = 1;
    }

    // Prep (single merged launch): fp16 + fragment-order retile
    prep_all<<<PREP_BLOCKS, 256>>>(fs, fp, gW1, eW1, gW2, eW2);

    // Layer 1 (fp16 tensor), writes H1 directly in gemm2 A-frag order
    gemm1_tc<<<dim3(NV * 4, BATCH / 128), 256, GEMM_SMEM>>>(gb1, eb1);
    // Layer 2
    gemm2_tc<<<dim3(NV, BATCH / 128), 256, GEMM_SMEM>>>(gb2, eb2);
    // Layer 3 + softmax/log_softmax + weighted sum (2 threads per token)
    final_kernel<<<BATCH / 128, 256, FIN_SMEM>>>(gW3, gb3, eW3, eb3, out, write_gate);
}

// round 9
// speedup vs baseline: 10.1210x; 1.0125x over previous
#include <cuda_runtime.h>
#include <cuda_fp16.h>
#include <cstdint>
#include <cstddef>

#define BATCH   16384
#define DIN     2048
#define DHALF   1024
#define H1DIM   512
#define H2DIM   128
#define NEXP    8
#define NCLS    10
#define NV      9

// ---------------------------------------------------------------------------
// Scratch (__device__ globals)
// ---------------------------------------------------------------------------
__device__ uint4 g_At [(size_t)128 * 128 * 8 * 32];
__device__ uint2 g_W1t[(size_t)36 * 128 * 16 * 32];
__device__ uint2 g_W2t[(size_t)9 * 32 * 16 * 32];
__device__ uint4 g_H1t[(size_t)9 * 128 * 32 * 8 * 32];
__device__ float g_H2 [(size_t)NV * BATCH * H2DIM];

// ---------------------------------------------------------------------------
// helpers
// ---------------------------------------------------------------------------
__device__ __forceinline__ uint32_t smem_u32(const void* p) {
    uint32_t a;
    asm("{ .reg .u64 t; cvta.to.shared.u64 t, %1; cvt.u32.u64 %0, t; }" : "=r"(a) : "l"(p));
    return a;
}

__device__ __forceinline__ uint32_t pack_h2(float x, float y) {
    __half2 h = __floats2half2_rn(x, y);
    return *(uint32_t*)&h;
}

#define CP16(ds, gs) \
    asm volatile("cp.async.cg.shared.global [%0], [%1], 16;" :: "r"(ds), "l"(gs))
#define CP_COMMIT()  asm volatile("cp.async.commit_group;" ::: "memory")
#define CP_WAIT2()   asm volatile("cp.async.wait_group 2;" ::: "memory")
#define CP_WAIT1()   asm volatile("cp.async.wait_group 1;" ::: "memory")
#define CP_WAIT0()   asm volatile("cp.async.wait_group 0;" ::: "memory")

// m16n8k16 fp16 MMA, fp32 accum, D += A*B (row.col)
__device__ __forceinline__ void mma16(float* d, const uint32_t* a, const uint32_t* b) {
    asm volatile(
        "mma.sync.aligned.m16n8k16.row.col.f32.f16.f16.f32 "
        "{%0,%1,%2,%3}, {%4,%5,%6,%7}, {%8,%9}, {%0,%1,%2,%3};"
        : "+f"(d[0]), "+f"(d[1]), "+f"(d[2]), "+f"(d[3])
        : "r"(a[0]), "r"(a[1]), "r"(a[2]), "r"(a[3]), "r"(b[0]), "r"(b[1]));
}

// ---------------------------------------------------------------------------
// Merged prep (unchanged from R8)
// ---------------------------------------------------------------------------
#define PA_BLOCKS   4096
#define PW1_BLOCKS  4608
#define PW2_BLOCKS  288
#define PREP_BLOCKS (PA_BLOCKS + PW1_BLOCKS + PW2_BLOCKS)

__device__ __forceinline__ void prep_W_body(
    const float* __restrict__ gw, const float* __restrict__ ew,
    uint2* dst, int K, int N, int kt, int nb, int v, int tid)
{
    const float* W = (v == 0) ? gw : (ew + (size_t)(v - 1) * K * N);
    const int KT = K / 16, NB = N / 128;
    const int k0 = kt * 16;

    for (int idx = tid; idx < 512; idx += 256) {
        const int nt = idx >> 5, l = idx & 31;
        const int c2 = 2 * (l & 3), g = l >> 2;
        const int n = nb * 128 + nt * 8 + g;
        uint2 o;
        o.x = pack_h2(W[(size_t)(k0 + c2)     * N + n], W[(size_t)(k0 + c2 + 1) * N + n]);
        o.y = pack_h2(W[(size_t)(k0 + c2 + 8) * N + n], W[(size_t)(k0 + c2 + 9) * N + n]);
        dst[((((size_t)v * NB + nb) * KT + kt) * 16 + nt) * 32 + l] = o;
    }
}

__global__ __launch_bounds__(256) void prep_all(
    const float* __restrict__ fs, const float* __restrict__ fp,
    const float* __restrict__ gW1, const float* __restrict__ eW1,
    const float* __restrict__ gW2, const float* __restrict__ eW2)
{
    const int bid = blockIdx.x;
    const int tid = threadIdx.x;

    if (bid < PA_BLOCKS) {
        const int mb = bid & 127, kq = bid >> 7;
        const int mt = tid >> 5, l = tid & 31;
        const int r = l >> 2, c2 = 2 * (l & 3);
        const int m0 = mb * 128 + mt * 16;

        #pragma unroll
        for (int t = 0; t < 4; t++) {
            const int kt = kq * 4 + t;
            const int k0 = kt * 16;
            const float* base = (k0 < DHALF) ? fs : fp;
            const int kk = (k0 < DHALF) ? k0 : k0 - DHALF;

            float2 p0 = *(const float2*)(base + (size_t)(m0 + r)     * DHALF + kk + c2);
            float2 p1 = *(const float2*)(base + (size_t)(m0 + r + 8) * DHALF + kk + c2);
            float2 p2 = *(const float2*)(base + (size_t)(m0 + r)     * DHALF + kk + c2 + 8);
            float2 p3 = *(const float2*)(base + (size_t)(m0 + r + 8) * DHALF + kk + c2 + 8);

            uint4 o;
            o.x = pack_h2(p0.x, p0.y);
            o.y = pack_h2(p1.x, p1.y);
            o.z = pack_h2(p2.x, p2.y);
            o.w = pack_h2(p3.x, p3.y);
            g_At[(((size_t)mb * 128 + kt) * 8 + mt) * 32 + l] = o;
        }
    } else if (bid < PA_BLOCKS + PW1_BLOCKS) {
        const int t = bid - PA_BLOCKS;
        const int kt = t & 127, nb = (t >> 7) & 3, v = t >> 9;
        prep_W_body(gW1, eW1, g_W1t, DIN, H1DIM, kt, nb, v, tid);
    } else {
        const int t = bid - (PA_BLOCKS + PW1_BLOCKS);
        const int kt = t & 31, v = t >> 5;
        prep_W_body(gW2, eW2, g_W2t, H1DIM, H2DIM, kt, 0, v, tid);
    }
}

// ---------------------------------------------------------------------------
// GEMM mainloop: block 128m x 128n x 32k/stage; 4 warps (2m x 2n), warp 64x64
// smem stage = A 8KB + B 8KB = 16KB; 4 stages = 64KB -> 2 CTAs/SM (128KB)
// 128 threads/CTA. LDS per HMMA: 128B (vs 192B at 64x32 warp tile).
// ---------------------------------------------------------------------------
#define STAGES       4
#define STAGE_BYTES  16384
#define GSTRIDE      8192
#define GEMM_SMEM    (STAGES * STAGE_BYTES)

__device__ __forceinline__ void issue_stage(uint32_t sbase, int stage,
                                            const char* gA, const char* gB, int tid)
{
    uint32_t sA = sbase + stage * STAGE_BYTES;
    uint32_t sB = sA + 8192;
    #pragma unroll
    for (int j = 0; j < 4; j++)
        CP16(sA + (uint32_t)(tid + j * 128) * 16, gA + (size_t)(tid + j * 128) * 16);
    #pragma unroll
    for (int j = 0; j < 4; j++)
        CP16(sB + (uint32_t)(tid + j * 128) * 16, gB + (size_t)(tid + j * 128) * 16);
}

__device__ __forceinline__ void compute_stage(const char* smem, int stage,
                                              int wm, int wn, int l,
                                              float acc[4][8][4])
{
    const char* sA = smem + stage * STAGE_BYTES;
    const char* sB = sA + 8192;
    #pragma unroll
    for (int ks = 0; ks < 2; ks++) {
        uint32_t a[4][4], b[8][2];
        #pragma unroll
        for (int i = 0; i < 4; i++) {
            uint4 av = *(const uint4*)(sA + (((ks * 8 + wm * 4 + i) * 32 + l) << 4));
            a[i][0] = av.x; a[i][1] = av.y; a[i][2] = av.z; a[i][3] = av.w;
        }
        #pragma unroll
        for (int j = 0; j < 8; j++) {
            uint2 bv = *(const uint2*)(sB + (((ks * 16 + wn * 8 + j) * 32 + l) << 3));
            b[j][0] = bv.x; b[j][1] = bv.y;
        }
        #pragma unroll
        for (int i = 0; i < 4; i++)
            #pragma unroll
            for (int j = 0; j < 8; j++)
                mma16(acc[i][j], a[i], b[j]);
    }
}

template<int NKB>
__device__ __forceinline__ void gemm_mainloop(
    uint32_t sbase, const char* smem, const char* gA0, const char* gB0,
    int tid, int wm, int wn, int l, float acc[4][8][4])
{
    issue_stage(sbase, 0, gA0,               gB0,               tid); CP_COMMIT();
    issue_stage(sbase, 1, gA0 + 1 * GSTRIDE, gB0 + 1 * GSTRIDE, tid); CP_COMMIT();
    issue_stage(sbase, 2, gA0 + 2 * GSTRIDE, gB0 + 2 * GSTRIDE, tid); CP_COMMIT();

    #pragma unroll 4
    for (int kb = 0; kb < NKB; kb++) {
        CP_WAIT2();
        __syncthreads();
        if (kb + 3 < NKB)
            issue_stage(sbase, (kb + 3) & (STAGES - 1),
                        gA0 + (size_t)(kb + 3) * GSTRIDE,
                        gB0 + (size_t)(kb + 3) * GSTRIDE, tid);
        CP_COMMIT();
        compute_stage(smem, kb & (STAGES - 1), wm, wn, l, acc);
    }
    CP_WAIT0();
}

// ---------------------------------------------------------------------------
// gemm1_tc: grid (36 = v*4+nb, 128 mb), 128 threads, warp 64x64
// ---------------------------------------------------------------------------
__global__ __launch_bounds__(128, 2) void gemm1_tc(
    const float* __restrict__ gb1, const float* __restrict__ eb1)
{
    extern __shared__ __align__(16) char smem[];
    const uint32_t sbase = smem_u32(smem);
    const int tid = threadIdx.x;
    const int w = tid >> 5, l = tid & 31;
    const int wm = w >> 1, wn = w & 1;
    const int v = blockIdx.x >> 2, nb = blockIdx.x & 3;
    const int mb = blockIdx.y;

    const char* gA0 = (const char*)g_At + (size_t)mb * 128 * 4096;
    const char* gB0 = (const char*)g_W1t + (size_t)(v * 4 + nb) * 128 * 4096;

    float acc[4][8][4];
    #pragma unroll
    for (int i = 0; i < 4; i++)
        #pragma unroll
        for (int j = 0; j < 8; j++)
            #pragma unroll
            for (int q = 0; q < 4; q++) acc[i][j][q] = 0.0f;

    gemm_mainloop<DIN / 32>(sbase, smem, gA0, gB0, tid, wm, wn, l, acc);

    // ---- epilogue: bias+relu+fp16, direct A-fragment store for gemm2 ----
    const float* bias = ((v == 0) ? gb1 : (eb1 + (size_t)(v - 1) * H1DIM)) + nb * 128;
    const int c2 = 2 * (l & 3);
    #pragma unroll
    for (int i = 0; i < 4; i++) {
        const int mt = wm * 4 + i;
        #pragma unroll
        for (int jk = 0; jk < 4; jk++) {
            uint4 o;
            {
                const int j = 2 * jk;
                const int cc = wn * 64 + j * 8 + c2;
                const float b0 = __ldg(bias + cc), b1 = __ldg(bias + cc + 1);
                o.x = pack_h2(fmaxf(acc[i][j][0] + b0, 0.0f), fmaxf(acc[i][j][1] + b1, 0.0f));
                o.y = pack_h2(fmaxf(acc[i][j][2] + b0, 0.0f), fmaxf(acc[i][j][3] + b1, 0.0f));
            }
            {
                const int j = 2 * jk + 1;
                const int cc = wn * 64 + j * 8 + c2;
                const float b0 = __ldg(bias + cc), b1 = __ldg(bias + cc + 1);
                o.z = pack_h2(fmaxf(acc[i][j][0] + b0, 0.0f), fmaxf(acc[i][j][1] + b1, 0.0f));
                o.w = pack_h2(fmaxf(acc[i][j][2] + b0, 0.0f), fmaxf(acc[i][j][3] + b1, 0.0f));
            }
            const int kt = nb * 8 + wn * 4 + jk;
            g_H1t[((((size_t)v * 128 + mb) * 32 + kt) * 8 + mt) * 32 + l] = o;
        }
    }
}

// ---------------------------------------------------------------------------
// gemm2_tc: grid (9, 128 mb), 128 threads, warp 64x64
// ---------------------------------------------------------------------------
__global__ __launch_bounds__(128, 2) void gemm2_tc(
    const float* __restrict__ gb2, const float* __restrict__ eb2)
{
    extern __shared__ __align__(16) char smem[];
    const uint32_t sbase = smem_u32(smem);
    const int tid = threadIdx.x;
    const int w = tid >> 5, l = tid & 31;
    const int wm = w >> 1, wn = w & 1;
    const int v = blockIdx.x;
    const int mb = blockIdx.y;

    const char* gA0 = (const char*)g_H1t + (size_t)(v * 128 + mb) * 32 * 4096;
    const char* gB0 = (const char*)g_W2t + (size_t)v * 32 * 4096;

    float acc[4][8][4];
    #pragma unroll
    for (int i = 0; i < 4; i++)
        #pragma unroll
        for (int j = 0; j < 8; j++)
            #pragma unroll
            for (int q = 0; q < 4; q++) acc[i][j][q] = 0.0f;

    gemm_mainloop<H1DIM / 32>(sbase, smem, gA0, gB0, tid, wm, wn, l, acc);

    // ---- epilogue: bias + relu, direct fp32 store ----
    const float* bias = (v == 0) ? gb2 : (eb2 + (size_t)(v - 1) * H2DIM);
    const int r = l >> 2, c2 = 2 * (l & 3);
    #pragma unroll
    for (int i = 0; i < 4; i++) {
        const int m = mb * 128 + wm * 64 + i * 16 + r;
        float* o0 = g_H2 + ((size_t)v * BATCH + m) * H2DIM;
        float* o1 = g_H2 + ((size_t)v * BATCH + m + 8) * H2DIM;
        #pragma unroll
        for (int j = 0; j < 8; j++) {
            const int n = wn * 64 + j * 8 + c2;
            const float b0 = __ldg(bias + n), b1 = __ldg(bias + n + 1);
            float2 u, d;
            u.x = fmaxf(acc[i][j][0] + b0, 0.0f);
            u.y = fmaxf(acc[i][j][1] + b1, 0.0f);
            d.x = fmaxf(acc[i][j][2] + b0, 0.0f);
            d.y = fmaxf(acc[i][j][3] + b1, 0.0f);
            *(float2*)(o0 + n) = u;
            *(float2*)(o1 + n) = d;
        }
    }
}

// ---------------------------------------------------------------------------
// final_kernel v3 (unchanged from R8)
// ---------------------------------------------------------------------------
#define FIN_TILE_STRIDE 132
#define FIN_TILE_BYTES  (128 * FIN_TILE_STRIDE * 4)
#define FIN_WG_OFF      (2 * FIN_TILE_BYTES)
#define FIN_WE_OFF      (FIN_WG_OFF + 128 * 8 * 4)
#define FIN_SP_OFF      (FIN_WE_OFF + 8 * 128 * 12 * 4)
#define FIN_SMEM        (FIN_SP_OFF + 128 * 12 * 4)

__global__ __launch_bounds__(256) void final_kernel(
    const float* __restrict__ gW3, const float* __restrict__ gb3,
    const float* __restrict__ eW3, const float* __restrict__ eb3,
    float* __restrict__ out, int write_gate)
{
    extern __shared__ __align__(16) char smem[];
    const uint32_t sbase = smem_u32(smem);
    const int tid = threadIdx.x;
    const int half = tid >> 7;
    const int tt = tid & 127;
    const int m0 = blockIdx.x * 128;

    float* tile0 = (float*)smem;
    float* tile1 = (float*)(smem + FIN_TILE_BYTES);
    float* wg = (float*)(smem + FIN_WG_OFF);
    float* we = (float*)(smem + FIN_WE_OFF);
    float* sp = (float*)(smem + FIN_SP_OFF);

    for (int i = tid; i < 128 * 8; i += 256) wg[i] = gW3[i];
    for (int i = tid; i < 8 * 128 * NCLS; i += 256) {
        const int e = i / (128 * NCLS);
        const int rem = i - e * 128 * NCLS;
        const int k = rem / NCLS, c = rem - k * NCLS;
        we[(e * 128 + k) * 12 + c] = eW3[i];
    }

    auto issue_tile = [&](uint32_t sdst, int v) {
        const float* src = g_H2 + (size_t)v * BATCH * H2DIM + (size_t)m0 * H2DIM;
        #pragma unroll
        for (int it = 0; it < 16; it++) {
            const int idx = tid + it * 256;
            const int row = idx >> 5, c4 = idx & 31;
            CP16(sdst + (uint32_t)(row * FIN_TILE_STRIDE + c4 * 4) * 4,
                 src + (size_t)row * H2DIM + c4 * 4);
        }
    };

    const uint32_t st0 = sbase;
    const uint32_t st1 = sbase + FIN_TILE_BYTES;

    issue_tile(st0, 0); CP_COMMIT();

    float gate[NEXP];
    float outc[NCLS];
    #pragma unroll
    for (int c = 0; c < NCLS; c++) outc[c] = 0.0f;

    for (int v = 0; v < NV; v++) {
        if (v + 1 < NV) { issue_tile((v & 1) ? st0 : st1, v + 1); CP_COMMIT(); }
        if (v + 1 < NV) { CP_WAIT1(); } else { CP_WAIT0(); }
        __syncthreads();

        const float* row = ((v & 1) ? tile1 : tile0)
                         + (size_t)tt * FIN_TILE_STRIDE + half * 64;

        if (v == 0) {
            float gl[NEXP];
            #pragma unroll
            for (int j = 0; j < NEXP; j++) gl[j] = 0.0f;
            const float* wgh = wg + half * 64 * 8;
            #pragma unroll 4
            for (int k4 = 0; k4 < 16; k4++) {
                const float4 h4 = *(const float4*)(row + k4 * 4);
                const float hv[4] = { h4.x, h4.y, h4.z, h4.w };
                #pragma unroll
                for (int q = 0; q < 4; q++) {
                    const float h = hv[q];
                    const float4 w0 = *(const float4*)(wgh + (k4 * 4 + q) * 8);
                    const float4 w1 = *(const float4*)(wgh + (k4 * 4 + q) * 8 + 4);
                    gl[0] += h * w0.x; gl[1] += h * w0.y; gl[2] += h * w0.z; gl[3] += h * w0.w;
                    gl[4] += h * w1.x; gl[5] += h * w1.y; gl[6] += h * w1.z; gl[7] += h * w1.w;
                }
            }
            if (half == 1) {
                #pragma unroll
                for (int j = 0; j < NEXP; j++) sp[tt * 12 + j] = gl[j];
            }
            __syncthreads();
            if (half == 0) {
                #pragma unroll
                for (int j = 0; j < NEXP; j++)
                    gl[j] += sp[tt * 12 + j] + __ldg(gb3 + j);
                float mx = gl[0];
                #pragma unroll
                for (int j = 1; j < NEXP; j++) mx = fmaxf(mx, gl[j]);
                float s = 0.0f;
                #pragma unroll
                for (int j = 0; j < NEXP; j++) { gate[j] = expf(gl[j] - mx); s += gate[j]; }
                const float inv = 1.0f / s;
                #pragma unroll
                for (int j = 0; j < NEXP; j++) gate[j] *= inv;
            }
        } else {
            const int e = v - 1;
            const float* w = we + ((size_t)e * 128 + half * 64) * 12;
            float le[NCLS];
            #pragma unroll
            for (int c = 0; c < NCLS; c++) le[c] = 0.0f;
            #pragma unroll 4
            for (int k4 = 0; k4 < 16; k4++) {
                const float4 h4 = *(const float4*)(row + k4 * 4);
                const float hv[4] = { h4.x, h4.y, h4.z, h4.w };
                #pragma unroll
                for (int q = 0; q < 4; q++) {
                    const float h = hv[q];
                    const float* wk = w + (k4 * 4 + q) * 12;
                    const float4 w0 = *(const float4*)(wk);
                    const float4 w1 = *(const float4*)(wk + 4);
                    const float2 w2 = *(const float2*)(wk + 8);
                    le[0] += h * w0.x; le[1] += h * w0.y; le[2] += h * w0.z; le[3] += h * w0.w;
                    le[4] += h * w1.x; le[5] += h * w1.y; le[6] += h * w1.z; le[7] += h * w1.w;
                    le[8] += h * w2.x; le[9] += h * w2.y;
                }
            }
            if (half == 1) {
                #pragma unroll
                for (int c = 0; c < NCLS; c++) sp[tt * 12 + c] = le[c];
            }
            __syncthreads();
            if (half == 0) {
                #pragma unroll
                for (int c = 0; c < NCLS; c++)
                    le[c] += sp[tt * 12 + c] + __ldg(eb3 + e * NCLS + c);
                float mxe = le[0];
                #pragma unroll
                for (int c = 1; c < NCLS; c++) mxe = fmaxf(mxe, le[c]);
                float se = 0.0f;
                #pragma unroll
                for (int c = 0; c < NCLS; c++) se += expf(le[c] - mxe);
                const float lse = mxe + logf(se);
                const float ge = gate[e];
                #pragma unroll
                for (int c = 0; c < NCLS; c++) outc[c] += ge * (le[c] - lse);
            }
        }
        __syncthreads();
    }

    if (half == 0) {
        const int m = m0 + tt;
        #pragma unroll
        for (int c = 0; c < NCLS; c++) out[(size_t)m * NCLS + c] = outc[c];
        if (write_gate) {
            float* gate_out = out + (size_t)BATCH * NCLS;
            #pragma unroll
            for (int j = 0; j < NEXP; j++) gate_out[(size_t)m * NEXP + j] = gate[j];
        }
    }
}

// ---------------------------------------------------------------------------
// Launch
// ---------------------------------------------------------------------------
extern "C" void kernel_launch(void* const* d_in, const int* in_sizes, int n_in,
                              void* d_out, int out_size)
{
    const float* fs  = (const float*)d_in[0];
    const float* fp  = (const float*)d_in[1];
    const float* gW1 = (const float*)d_in[2];
    const float* gb1 = (const float*)d_in[3];
    const float* gW2 = (const float*)d_in[4];
    const float* gb2 = (const float*)d_in[5];
    const float* gW3 = (const float*)d_in[6];
    const float* gb3 = (const float*)d_in[7];
    const float* eW1 = (const float*)d_in[8];
    const float* eb1 = (const float*)d_in[9];
    const float* eW2 = (const float*)d_in[10];
    const float* eb2 = (const float*)d_in[11];
    const float* eW3 = (const float*)d_in[12];
    const float* eb3 = (const float*)d_in[13];
    float* out = (float*)d_out;

    const int write_gate = (out_size >= BATCH * (NCLS + NEXP)) ? 1 : 0;

    static int attr_done = 0;
    if (!attr_done) {
        cudaFuncSetAttribute(gemm1_tc, cudaFuncAttributeMaxDynamicSharedMemorySize, GEMM_SMEM);
        cudaFuncSetAttribute(gemm2_tc, cudaFuncAttributeMaxDynamicSharedMemorySize, GEMM_SMEM);
        cudaFuncSetAttribute(final_kernel, cudaFuncAttributeMaxDynamicSharedMemorySize, FIN_SMEM);
        attr_done = 1;
    }

    // Prep (single merged launch)
    prep_all<<<PREP_BLOCKS, 256>>>(fs, fp, gW1, eW1, gW2, eW2);

    // Layer 1 (fp16 tensor, 64x64 warp tile), H1 stored in gemm2 A-frag order
    gemm1_tc<<<dim3(NV * 4, BATCH / 128), 128, GEMM_SMEM>>>(gb1, eb1);
    // Layer 2
    gemm2_tc<<<dim3(NV, BATCH / 128), 128, GEMM_SMEM>>>(gb2, eb2);
    // Layer 3 + softmax/log_softmax + weighted sum
    final_kernel<<<BATCH / 128, 256, FIN_SMEM>>>(gW3, gb3, eW3, eb3, out, write_gate);
}

// round 11
// speedup vs baseline: 10.3270x; 1.0204x over previous
#include <cuda_runtime.h>
#include <cuda_fp16.h>
#include <cstdint>
#include <cstddef>

#define BATCH   16384
#define DIN     2048
#define DHALF   1024
#define H1DIM   512
#define H2DIM   128
#define NEXP    8
#define NCLS    10
#define NV      9

// ---------------------------------------------------------------------------
// Scratch (__device__ globals)
// g_At : A fp16, A-frag order  [mb=128][kt=128][mt=8][lane=32] uint4
// g_W1t: W1 fp16, PAIRED B-frag order [v*4+nb=36][kt=128][ntp=8][lane=32] uint4
//        uint4 = {frag(ntp,lo8).r0, .r1, frag(ntp,hi8).r0, .r1}
// g_W2t: W2 fp16, PAIRED B-frag order [v=9][kt=32][ntp=8][lane=32] uint4
// g_H1t: H1 fp16, A-frag order [v=9][mb=128][kt=32][mt=8][lane=32] uint4
// g_H2 : fp32 row-major [v][m][128]
// ---------------------------------------------------------------------------
__device__ uint4 g_At [(size_t)128 * 128 * 8 * 32];
__device__ uint4 g_W1t[(size_t)36 * 128 * 8 * 32];
__device__ uint4 g_W2t[(size_t)9 * 32 * 8 * 32];
__device__ uint4 g_H1t[(size_t)9 * 128 * 32 * 8 * 32];
__device__ float g_H2 [(size_t)NV * BATCH * H2DIM];

// ---------------------------------------------------------------------------
// helpers
// ---------------------------------------------------------------------------
__device__ __forceinline__ uint32_t smem_u32(const void* p) {
    uint32_t a;
    asm("{ .reg .u64 t; cvta.to.shared.u64 t, %1; cvt.u32.u64 %0, t; }" : "=r"(a) : "l"(p));
    return a;
}

__device__ __forceinline__ uint32_t pack_h2(float x, float y) {
    __half2 h = __floats2half2_rn(x, y);
    return *(uint32_t*)&h;
}

#define CP16(ds, gs) \
    asm volatile("cp.async.cg.shared.global [%0], [%1], 16;" :: "r"(ds), "l"(gs))
#define CP_COMMIT()  asm volatile("cp.async.commit_group;" ::: "memory")
#define CP_WAIT2()   asm volatile("cp.async.wait_group 2;" ::: "memory")
#define CP_WAIT1()   asm volatile("cp.async.wait_group 1;" ::: "memory")
#define CP_WAIT0()   asm volatile("cp.async.wait_group 0;" ::: "memory")

// m16n8k16 fp16 MMA, fp32 accum, D += A*B (row.col)
__device__ __forceinline__ void mma16(float* d, const uint32_t* a, const uint32_t* b) {
    asm volatile(
        "mma.sync.aligned.m16n8k16.row.col.f32.f16.f16.f32 "
        "{%0,%1,%2,%3}, {%4,%5,%6,%7}, {%8,%9}, {%0,%1,%2,%3};"
        : "+f"(d[0]), "+f"(d[1]), "+f"(d[2]), "+f"(d[3])
        : "r"(a[0]), "r"(a[1]), "r"(a[2]), "r"(a[3]), "r"(b[0]), "r"(b[1]));
}

// ---------------------------------------------------------------------------
// Merged prep
// ---------------------------------------------------------------------------
#define PA_BLOCKS   4096
#define PW1_BLOCKS  4608
#define PW2_BLOCKS  288
#define PREP_BLOCKS (PA_BLOCKS + PW1_BLOCKS + PW2_BLOCKS)

// paired B-frag: for ntp (16 n-cols), pack frag of n=[ntp*16, +8) and [ntp*16+8, +8)
__device__ __forceinline__ void prep_W_body(
    const float* __restrict__ gw, const float* __restrict__ ew,
    uint4* dst, int K, int N, int kt, int nb, int v, int tid)
{
    const float* W = (v == 0) ? gw : (ew + (size_t)(v - 1) * K * N);
    const int KT = K / 16, NB = N / 128;
    const int k0 = kt * 16;

    if (tid < 256) {
        const int ntp = tid >> 5, l = tid & 31;
        const int c2 = 2 * (l & 3), g = l >> 2;
        const int n0 = nb * 128 + ntp * 16 + g;
        const int n1 = n0 + 8;
        uint4 o;
        o.x = pack_h2(W[(size_t)(k0 + c2)     * N + n0], W[(size_t)(k0 + c2 + 1) * N + n0]);
        o.y = pack_h2(W[(size_t)(k0 + c2 + 8) * N + n0], W[(size_t)(k0 + c2 + 9) * N + n0]);
        o.z = pack_h2(W[(size_t)(k0 + c2)     * N + n1], W[(size_t)(k0 + c2 + 1) * N + n1]);
        o.w = pack_h2(W[(size_t)(k0 + c2 + 8) * N + n1], W[(size_t)(k0 + c2 + 9) * N + n1]);
        dst[((((size_t)v * NB + nb) * KT + kt) * 8 + ntp) * 32 + l] = o;
    }
}

__global__ __launch_bounds__(256) void prep_all(
    const float* __restrict__ fs, const float* __restrict__ fp,
    const float* __restrict__ gW1, const float* __restrict__ eW1,
    const float* __restrict__ gW2, const float* __restrict__ eW2)
{
    const int bid = blockIdx.x;
    const int tid = threadIdx.x;

    if (bid < PA_BLOCKS) {
        const int mb = bid & 127, kq = bid >> 7;
        const int mt = tid >> 5, l = tid & 31;
        const int r = l >> 2, c2 = 2 * (l & 3);
        const int m0 = mb * 128 + mt * 16;

        #pragma unroll
        for (int t = 0; t < 4; t++) {
            const int kt = kq * 4 + t;
            const int k0 = kt * 16;
            const float* base = (k0 < DHALF) ? fs : fp;
            const int kk = (k0 < DHALF) ? k0 : k0 - DHALF;

            float2 p0 = *(const float2*)(base + (size_t)(m0 + r)     * DHALF + kk + c2);
            float2 p1 = *(const float2*)(base + (size_t)(m0 + r + 8) * DHALF + kk + c2);
            float2 p2 = *(const float2*)(base + (size_t)(m0 + r)     * DHALF + kk + c2 + 8);
            float2 p3 = *(const float2*)(base + (size_t)(m0 + r + 8) * DHALF + kk + c2 + 8);

            uint4 o;
            o.x = pack_h2(p0.x, p0.y);
            o.y = pack_h2(p1.x, p1.y);
            o.z = pack_h2(p2.x, p2.y);
            o.w = pack_h2(p3.x, p3.y);
            g_At[(((size_t)mb * 128 + kt) * 8 + mt) * 32 + l] = o;
        }
    } else if (bid < PA_BLOCKS + PW1_BLOCKS) {
        const int t = bid - PA_BLOCKS;
        const int kt = t & 127, nb = (t >> 7) & 3, v = t >> 9;
        prep_W_body(gW1, eW1, g_W1t, DIN, H1DIM, kt, nb, v, tid);
    } else {
        const int t = bid - (PA_BLOCKS + PW1_BLOCKS);
        const int kt = t & 31, v = t >> 5;
        prep_W_body(gW2, eW2, g_W2t, H1DIM, H2DIM, kt, 0, v, tid);
    }
}

// ---------------------------------------------------------------------------
// GEMM mainloop: block 128m x 128n x 32k/stage; 4 warps (2m x 2n), warp 64x64
// smem stage = A 8KB + B 8KB = 16KB; 4 stages = 64KB -> 2 CTAs/SM (R9 skeleton)
// B loads paired: 4 x LDS.128 per k16 per warp (corrected address math).
// Stage B layout: [kt(2) x 4096][ntp(8) x 512][lane(32) x 16]
// Warp wn covers n [wn*64, wn*64+64) = ntp [wn*4, wn*4+4).
// ---------------------------------------------------------------------------
#define STAGES       4
#define STAGE_BYTES  16384
#define GSTRIDE      8192
#define GEMM_SMEM    (STAGES * STAGE_BYTES)   // 65536

__device__ __forceinline__ void issue_stage(uint32_t sbase, int stage,
                                            const char* gA, const char* gB, int tid)
{
    uint32_t sA = sbase + stage * STAGE_BYTES;
    uint32_t sB = sA + 8192;
    #pragma unroll
    for (int j = 0; j < 4; j++)
        CP16(sA + (uint32_t)(tid + j * 128) * 16, gA + (size_t)(tid + j * 128) * 16);
    #pragma unroll
    for (int j = 0; j < 4; j++)
        CP16(sB + (uint32_t)(tid + j * 128) * 16, gB + (size_t)(tid + j * 128) * 16);
}

__device__ __forceinline__ void compute_stage(const char* smem, int stage,
                                              int wm, int wn, int l,
                                              float acc[4][8][4])
{
    const char* sA = smem + stage * STAGE_BYTES;
    const char* sB = sA + 8192;
    #pragma unroll
    for (int ks = 0; ks < 2; ks++) {
        uint32_t a[4][4], b[8][2];
        #pragma unroll
        for (int i = 0; i < 4; i++) {
            uint4 av = *(const uint4*)(sA + (((ks * 8 + wm * 4 + i) * 32 + l) << 4));
            a[i][0] = av.x; a[i][1] = av.y; a[i][2] = av.z; a[i][3] = av.w;
        }
        #pragma unroll
        for (int p = 0; p < 4; p++) {
            // ks*4096 + (wn*4 + p)*512 + l*16
            uint4 bv = *(const uint4*)(sB + ks * 4096 + ((wn * 4 + p) * 32 + l) * 16);
            b[2*p][0]   = bv.x; b[2*p][1]   = bv.y;
            b[2*p+1][0] = bv.z; b[2*p+1][1] = bv.w;
        }
        #pragma unroll
        for (int i = 0; i < 4; i++)
            #pragma unroll
            for (int j = 0; j < 8; j++)
                mma16(acc[i][j], a[i], b[j]);
    }
}

template<int NKB>
__device__ __forceinline__ void gemm_mainloop(
    uint32_t sbase, const char* smem, const char* gA0, const char* gB0,
    int tid, int wm, int wn, int l, float acc[4][8][4])
{
    issue_stage(sbase, 0, gA0,               gB0,               tid); CP_COMMIT();
    issue_stage(sbase, 1, gA0 + 1 * GSTRIDE, gB0 + 1 * GSTRIDE, tid); CP_COMMIT();
    issue_stage(sbase, 2, gA0 + 2 * GSTRIDE, gB0 + 2 * GSTRIDE, tid); CP_COMMIT();

    #pragma unroll 4
    for (int kb = 0; kb < NKB; kb++) {
        CP_WAIT2();
        __syncthreads();
        if (kb + 3 < NKB)
            issue_stage(sbase, (kb + 3) & (STAGES - 1),
                        gA0 + (size_t)(kb + 3) * GSTRIDE,
                        gB0 + (size_t)(kb + 3) * GSTRIDE, tid);
        CP_COMMIT();
        compute_stage(smem, kb & (STAGES - 1), wm, wn, l, acc);
    }
    CP_WAIT0();
}

// ---------------------------------------------------------------------------
// gemm1_tc: grid (36 = v*4+nb, 128 mb), 128 threads, warp 64x64
// ---------------------------------------------------------------------------
__global__ __launch_bounds__(128, 2) void gemm1_tc(
    const float* __restrict__ gb1, const float* __restrict__ eb1)
{
    extern __shared__ __align__(16) char smem[];
    const uint32_t sbase = smem_u32(smem);
    const int tid = threadIdx.x;
    const int w = tid >> 5, l = tid & 31;
    const int wm = w >> 1, wn = w & 1;
    const int v = blockIdx.x >> 2, nb = blockIdx.x & 3;
    const int mb = blockIdx.y;

    const char* gA0 = (const char*)g_At + (size_t)mb * 128 * 4096;
    const char* gB0 = (const char*)g_W1t + (size_t)(v * 4 + nb) * 128 * 4096;

    float acc[4][8][4];
    #pragma unroll
    for (int i = 0; i < 4; i++)
        #pragma unroll
        for (int j = 0; j < 8; j++)
            #pragma unroll
            for (int q = 0; q < 4; q++) acc[i][j][q] = 0.0f;

    gemm_mainloop<DIN / 32>(sbase, smem, gA0, gB0, tid, wm, wn, l, acc);

    // ---- epilogue: bias+relu+fp16, direct A-fragment store for gemm2 ----
    const float* bias = ((v == 0) ? gb1 : (eb1 + (size_t)(v - 1) * H1DIM)) + nb * 128;
    const int c2 = 2 * (l & 3);
    #pragma unroll
    for (int i = 0; i < 4; i++) {
        const int mt = wm * 4 + i;
        #pragma unroll
        for (int jk = 0; jk < 4; jk++) {
            uint4 o;
            {
                const int j = 2 * jk;
                const int cc = wn * 64 + j * 8 + c2;
                const float b0 = __ldg(bias + cc), b1 = __ldg(bias + cc + 1);
                o.x = pack_h2(fmaxf(acc[i][j][0] + b0, 0.0f), fmaxf(acc[i][j][1] + b1, 0.0f));
                o.y = pack_h2(fmaxf(acc[i][j][2] + b0, 0.0f), fmaxf(acc[i][j][3] + b1, 0.0f));
            }
            {
                const int j = 2 * jk + 1;
                const int cc = wn * 64 + j * 8 + c2;
                const float b0 = __ldg(bias + cc), b1 = __ldg(bias + cc + 1);
                o.z = pack_h2(fmaxf(acc[i][j][0] + b0, 0.0f), fmaxf(acc[i][j][1] + b1, 0.0f));
                o.w = pack_h2(fmaxf(acc[i][j][2] + b0, 0.0f), fmaxf(acc[i][j][3] + b1, 0.0f));
            }
            const int kt = nb * 8 + wn * 4 + jk;
            g_H1t[((((size_t)v * 128 + mb) * 32 + kt) * 8 + mt) * 32 + l] = o;
        }
    }
}

// ---------------------------------------------------------------------------
// gemm2_tc: grid (9, 128 mb), 128 threads, warp 64x64
// ---------------------------------------------------------------------------
__global__ __launch_bounds__(128, 2) void gemm2_tc(
    const float* __restrict__ gb2, const float* __restrict__ eb2)
{
    extern __shared__ __align__(16) char smem[];
    const uint32_t sbase = smem_u32(smem);
    const int tid = threadIdx.x;
    const int w = tid >> 5, l = tid & 31;
    const int wm = w >> 1, wn = w & 1;
    const int v = blockIdx.x;
    const int mb = blockIdx.y;

    const char* gA0 = (const char*)g_H1t + (size_t)(v * 128 + mb) * 32 * 4096;
    const char* gB0 = (const char*)g_W2t + (size_t)v * 32 * 4096;

    float acc[4][8][4];
    #pragma unroll
    for (int i = 0; i < 4; i++)
        #pragma unroll
        for (int j = 0; j < 8; j++)
            #pragma unroll
            for (int q = 0; q < 4; q++) acc[i][j][q] = 0.0f;

    gemm_mainloop<H1DIM / 32>(sbase, smem, gA0, gB0, tid, wm, wn, l, acc);

    // ---- epilogue: bias + relu, direct fp32 store ----
    const float* bias = (v == 0) ? gb2 : (eb2 + (size_t)(v - 1) * H2DIM);
    const int r = l >> 2, c2 = 2 * (l & 3);
    #pragma unroll
    for (int i = 0; i < 4; i++) {
        const int m = mb * 128 + wm * 64 + i * 16 + r;
        float* o0 = g_H2 + ((size_t)v * BATCH + m) * H2DIM;
        float* o1 = g_H2 + ((size_t)v * BATCH + m + 8) * H2DIM;
        #pragma unroll
        for (int j = 0; j < 8; j++) {
            const int n = wn * 64 + j * 8 + c2;
            const float b0 = __ldg(bias + n), b1 = __ldg(bias + n + 1);
            float2 u, d;
            u.x = fmaxf(acc[i][j][0] + b0, 0.0f);
            u.y = fmaxf(acc[i][j][1] + b1, 0.0f);
            d.x = fmaxf(acc[i][j][2] + b0, 0.0f);
            d.y = fmaxf(acc[i][j][3] + b1, 0.0f);
            *(float2*)(o0 + n) = u;
            *(float2*)(o1 + n) = d;
        }
    }
}

// ---------------------------------------------------------------------------
// final_kernel v3 (unchanged from R9)
// ---------------------------------------------------------------------------
#define FIN_TILE_STRIDE 132
#define FIN_TILE_BYTES  (128 * FIN_TILE_STRIDE * 4)
#define FIN_WG_OFF      (2 * FIN_TILE_BYTES)
#define FIN_WE_OFF      (FIN_WG_OFF + 128 * 8 * 4)
#define FIN_SP_OFF      (FIN_WE_OFF + 8 * 128 * 12 * 4)
#define FIN_SMEM        (FIN_SP_OFF + 128 * 12 * 4)

__global__ __launch_bounds__(256) void final_kernel(
    const float* __restrict__ gW3, const float* __restrict__ gb3,
    const float* __restrict__ eW3, const float* __restrict__ eb3,
    float* __restrict__ out, int write_gate)
{
    extern __shared__ __align__(16) char smem[];
    const uint32_t sbase = smem_u32(smem);
    const int tid = threadIdx.x;
    const int half = tid >> 7;
    const int tt = tid & 127;
    const int m0 = blockIdx.x * 128;

    float* tile0 = (float*)smem;
    float* tile1 = (float*)(smem + FIN_TILE_BYTES);
    float* wg = (float*)(smem + FIN_WG_OFF);
    float* we = (float*)(smem + FIN_WE_OFF);
    float* sp = (float*)(smem + FIN_SP_OFF);

    for (int i = tid; i < 128 * 8; i += 256) wg[i] = gW3[i];
    for (int i = tid; i < 8 * 128 * NCLS; i += 256) {
        const int e = i / (128 * NCLS);
        const int rem = i - e * 128 * NCLS;
        const int k = rem / NCLS, c = rem - k * NCLS;
        we[(e * 128 + k) * 12 + c] = eW3[i];
    }

    auto issue_tile = [&](uint32_t sdst, int v) {
        const float* src = g_H2 + (size_t)v * BATCH * H2DIM + (size_t)m0 * H2DIM;
        #pragma unroll
        for (int it = 0; it < 16; it++) {
            const int idx = tid + it * 256;
            const int row = idx >> 5, c4 = idx & 31;
            CP16(sdst + (uint32_t)(row * FIN_TILE_STRIDE + c4 * 4) * 4,
                 src + (size_t)row * H2DIM + c4 * 4);
        }
    };

    const uint32_t st0 = sbase;
    const uint32_t st1 = sbase + FIN_TILE_BYTES;

    issue_tile(st0, 0); CP_COMMIT();

    float gate[NEXP];
    float outc[NCLS];
    #pragma unroll
    for (int c = 0; c < NCLS; c++) outc[c] = 0.0f;

    for (int v = 0; v < NV; v++) {
        if (v + 1 < NV) { issue_tile((v & 1) ? st0 : st1, v + 1); CP_COMMIT(); }
        if (v + 1 < NV) { CP_WAIT1(); } else { CP_WAIT0(); }
        __syncthreads();

        const float* row = ((v & 1) ? tile1 : tile0)
                         + (size_t)tt * FIN_TILE_STRIDE + half * 64;

        if (v == 0) {
            float gl[NEXP];
            #pragma unroll
            for (int j = 0; j < NEXP; j++) gl[j] = 0.0f;
            const float* wgh = wg + half * 64 * 8;
            #pragma unroll 4
            for (int k4 = 0; k4 < 16; k4++) {
                const float4 h4 = *(const float4*)(row + k4 * 4);
                const float hv[4] = { h4.x, h4.y, h4.z, h4.w };
                #pragma unroll
                for (int q = 0; q < 4; q++) {
                    const float h = hv[q];
                    const float4 w0 = *(const float4*)(wgh + (k4 * 4 + q) * 8);
                    const float4 w1 = *(const float4*)(wgh + (k4 * 4 + q) * 8 + 4);
                    gl[0] += h * w0.x; gl[1] += h * w0.y; gl[2] += h * w0.z; gl[3] += h * w0.w;
                    gl[4] += h * w1.x; gl[5] += h * w1.y; gl[6] += h * w1.z; gl[7] += h * w1.w;
                }
            }
            if (half == 1) {
                #pragma unroll
                for (int j = 0; j < NEXP; j++) sp[tt * 12 + j] = gl[j];
            }
            __syncthreads();
            if (half == 0) {
                #pragma unroll
                for (int j = 0; j < NEXP; j++)
                    gl[j] += sp[tt * 12 + j] + __ldg(gb3 + j);
                float mx = gl[0];
                #pragma unroll
                for (int j = 1; j < NEXP; j++) mx = fmaxf(mx, gl[j]);
                float s = 0.0f;
                #pragma unroll
                for (int j = 0; j < NEXP; j++) { gate[j] = expf(gl[j] - mx); s += gate[j]; }
                const float inv = 1.0f / s;
                #pragma unroll
                for (int j = 0; j < NEXP; j++) gate[j] *= inv;
            }
        } else {
            const int e = v - 1;
            const float* w = we + ((size_t)e * 128 + half * 64) * 12;
            float le[NCLS];
            #pragma unroll
            for (int c = 0; c < NCLS; c++) le[c] = 0.0f;
            #pragma unroll 4
            for (int k4 = 0; k4 < 16; k4++) {
                const float4 h4 = *(const float4*)(row + k4 * 4);
                const float hv[4] = { h4.x, h4.y, h4.z, h4.w };
                #pragma unroll
                for (int q = 0; q < 4; q++) {
                    const float h = hv[q];
                    const float* wk = w + (k4 * 4 + q) * 12;
                    const float4 w0 = *(const float4*)(wk);
                    const float4 w1 = *(const float4*)(wk + 4);
                    const float2 w2 = *(const float2*)(wk + 8);
                    le[0] += h * w0.x; le[1] += h * w0.y; le[2] += h * w0.z; le[3] += h * w0.w;
                    le[4] += h * w1.x; le[5] += h * w1.y; le[6] += h * w1.z; le[7] += h * w1.w;
                    le[8] += h * w2.x; le[9] += h * w2.y;
                }
            }
            if (half == 1) {
                #pragma unroll
                for (int c = 0; c < NCLS; c++) sp[tt * 12 + c] = le[c];
            }
            __syncthreads();
            if (half == 0) {
                #pragma unroll
                for (int c = 0; c < NCLS; c++)
                    le[c] += sp[tt * 12 + c] + __ldg(eb3 + e * NCLS + c);
                float mxe = le[0];
                #pragma unroll
                for (int c = 1; c < NCLS; c++) mxe = fmaxf(mxe, le[c]);
                float se = 0.0f;
                #pragma unroll
                for (int c = 0; c < NCLS; c++) se += expf(le[c] - mxe);
                const float lse = mxe + logf(se);
                const float ge = gate[e];
                #pragma unroll
                for (int c = 0; c < NCLS; c++) outc[c] += ge * (le[c] - lse);
            }
        }
        __syncthreads();
    }

    if (half == 0) {
        const int m = m0 + tt;
        #pragma unroll
        for (int c = 0; c < NCLS; c++) out[(size_t)m * NCLS + c] = outc[c];
        if (write_gate) {
            float* gate_out = out + (size_t)BATCH * NCLS;
            #pragma unroll
            for (int j = 0; j < NEXP; j++) gate_out[(size_t)m * NEXP + j] = gate[j];
        }
    }
}

// ---------------------------------------------------------------------------
// Launch
// ---------------------------------------------------------------------------
extern "C" void kernel_launch(void* const* d_in, const int* in_sizes, int n_in,
                              void* d_out, int out_size)
{
    const float* fs  = (const float*)d_in[0];
    const float* fp  = (const float*)d_in[1];
    const float* gW1 = (const float*)d_in[2];
    const float* gb1 = (const float*)d_in[3];
    const float* gW2 = (const float*)d_in[4];
    const float* gb2 = (const float*)d_in[5];
    const float* gW3 = (const float*)d_in[6];
    const float* gb3 = (const float*)d_in[7];
    const float* eW1 = (const float*)d_in[8];
    const float* eb1 = (const float*)d_in[9];
    const float* eW2 = (const float*)d_in[10];
    const float* eb2 = (const float*)d_in[11];
    const float* eW3 = (const float*)d_in[12];
    const float* eb3 = (const float*)d_in[13];
    float* out = (float*)d_out;

    const int write_gate = (out_size >= BATCH * (NCLS + NEXP)) ? 1 : 0;

    static int attr_done = 0;
    if (!attr_done) {
        cudaFuncSetAttribute(gemm1_tc, cudaFuncAttributeMaxDynamicSharedMemorySize, GEMM_SMEM);
        cudaFuncSetAttribute(gemm2_tc, cudaFuncAttributeMaxDynamicSharedMemorySize, GEMM_SMEM);
        cudaFuncSetAttribute(final_kernel, cudaFuncAttributeMaxDynamicSharedMemorySize, FIN_SMEM);
        attr_done = 1;
    }

    // Prep (single merged launch)
    prep_all<<<PREP_BLOCKS, 256>>>(fs, fp, gW1, eW1, gW2, eW2);

    // Layer 1 (fp16 tensor, 64x64 warp tile, paired-B, 4-stage pipeline)
    gemm1_tc<<<dim3(NV * 4, BATCH / 128), 128, GEMM_SMEM>>>(gb1, eb1);
    // Layer 2
    gemm2_tc<<<dim3(NV, BATCH / 128), 128, GEMM_SMEM>>>(gb2, eb2);
    // Layer 3 + softmax/log_softmax + weighted sum
    final_kernel<<<BATCH / 128, 256, FIN_SMEM>>>(gW3, gb3, eW3, eb3, out, write_gate);
}